// round 10
// baseline (speedup 1.0000x reference)
#include <cuda_runtime.h>

#define BB 4
#define FF 32
#define CC 4096
#define TT 32
#define EE 65536
#define KK 9
#define NSEG 1024               // T*F floats per (b,c) tile
#define NTOT (BB*FF*CC*TT)      // 16777216
#define INVN (1.0f / 131072.0f) // 1/(CC*TT)

// ---------------- scratch (device globals; no allocs allowed) ----------------
__device__ float g_dis[CC];
__device__ int   g_off[CC + 1];
__device__ int   g_srcS[EE];     // CSR-sorted source node per slot
__device__ float g_nrmS[EE];     // CSR-sorted edge norm per slot
__device__ float g_buf0[NTOT];   // x_lin
__device__ float g_buf1[NTOT];   // h1 -> overwritten in-place by conv out
__device__ float g_s1[BB*FF], g_q1[BB*FF], g_s2[BB*FF], g_q2[BB*FF];

// ---------------- packed f32x2 helpers ----------------
__device__ __forceinline__ unsigned long long pack2(float x, float y) {
    unsigned long long r;
    asm("mov.b64 %0, {%1,%2};" : "=l"(r) : "f"(x), "f"(y));
    return r;
}
__device__ __forceinline__ void unpack2(unsigned long long v, float& x, float& y) {
    asm("mov.b64 {%0,%1}, %2;" : "=f"(x), "=f"(y) : "l"(v));
}
__device__ __forceinline__ unsigned long long fma2(unsigned long long a,
                                                   unsigned long long b,
                                                   unsigned long long c) {
    unsigned long long d;
    asm("fma.rn.f32x2 %0, %1, %2, %3;" : "=l"(d) : "l"(a), "l"(b), "l"(c));
    return d;
}

// ---------------- 1: x_lin[b,c,t,g] = sum_f x[b,f,c,t] * W[f,g] --------------
__global__ void k_xlin(const float* __restrict__ x, const float* __restrict__ W) {
    __shared__ float xs[32 * 33];
    __shared__ float ws[1024];          // [f][g]
    int tid = threadIdx.x;
    int bc = blockIdx.x;
    int b = bc >> 12, c = bc & (CC - 1);
    ((float4*)ws)[tid] = ((const float4*)W)[tid];
    int lf = tid >> 3, lt0 = (tid & 7) * 4;
    float4 xv = *(const float4*)&x[(((size_t)b * FF + lf) * CC + c) * TT + lt0];
    xs[(lt0 + 0) * 33 + lf] = xv.x;
    xs[(lt0 + 1) * 33 + lf] = xv.y;
    xs[(lt0 + 2) * 33 + lf] = xv.z;
    xs[(lt0 + 3) * 33 + lf] = xv.w;
    __syncthreads();
    int t = tid >> 3, g0 = (tid & 7) * 4;
    unsigned long long a0 = pack2(0.f, 0.f), a1 = pack2(0.f, 0.f);
#pragma unroll
    for (int f = 0; f < 32; ++f) {
        float z = xs[t * 33 + f];
        unsigned long long zz = pack2(z, z);
        ulonglong2 w2 = *(const ulonglong2*)&ws[f * 32 + g0];
        a0 = fma2(zz, w2.x, a0);
        a1 = fma2(zz, w2.y, a1);
    }
    float4 o;
    unpack2(a0, o.x, o.y);
    unpack2(a1, o.z, o.w);
    *(float4*)&g_buf0[((size_t)b * CC + c) * NSEG + (size_t)tid * 4] = o;
}

// ---------------- 2: fused prep + degree + scan + CSR fill -------------------
// Single block, 1024 threads. Produces g_dis, g_off, g_srcS, g_nrmS; zeroes stats.
__global__ void k_setup(const int* __restrict__ ei, const float* __restrict__ ew) {
    __shared__ float s_deg[CC];         // deg, then overwritten with dis
    __shared__ int   s_cnt[CC];         // counts, then running CSR positions
    __shared__ int   s_scan[1024];
    int tid = threadIdx.x;
#pragma unroll
    for (int i = tid; i < CC; i += 1024) { s_deg[i] = 1.0f; s_cnt[i] = 0; }
    if (tid < BB * FF) {
        g_s1[tid] = 0.f; g_q1[tid] = 0.f; g_s2[tid] = 0.f; g_q2[tid] = 0.f;
    }
    __syncthreads();
    // pass 1: degree + bucket counts
#pragma unroll 4
    for (int e = tid; e < EE; e += 1024) {
        int d = ei[EE + e];
        atomicAdd(&s_deg[d], ew[e]);
        atomicAdd(&s_cnt[d], 1);
    }
    __syncthreads();
    // scan (4 nodes per thread)
    int c0 = tid * 4;
    int l0 = s_cnt[c0], l1 = s_cnt[c0+1], l2 = s_cnt[c0+2], l3 = s_cnt[c0+3];
    int tot = l0 + l1 + l2 + l3;
    s_scan[tid] = tot;
    __syncthreads();
    for (int d = 1; d < 1024; d <<= 1) {
        int v = 0;
        if (tid >= d) v = s_scan[tid - d];
        __syncthreads();
        if (tid >= d) s_scan[tid] += v;
        __syncthreads();
    }
    int excl = s_scan[tid] - tot;
    g_off[c0]   = excl;
    g_off[c0+1] = excl + l0;
    g_off[c0+2] = excl + l0 + l1;
    g_off[c0+3] = excl + l0 + l1 + l2;
    if (tid == 1023) g_off[CC] = s_scan[1023];
    // own quad: overwrite counts with start offsets, deg with dis
    s_cnt[c0]   = excl;
    s_cnt[c0+1] = excl + l0;
    s_cnt[c0+2] = excl + l0 + l1;
    s_cnt[c0+3] = excl + l0 + l1 + l2;
    float d0 = rsqrtf(s_deg[c0]),   d1 = rsqrtf(s_deg[c0+1]);
    float d2 = rsqrtf(s_deg[c0+2]), d3 = rsqrtf(s_deg[c0+3]);
    s_deg[c0] = d0; s_deg[c0+1] = d1; s_deg[c0+2] = d2; s_deg[c0+3] = d3;
    g_dis[c0] = d0; g_dis[c0+1] = d1; g_dis[c0+2] = d2; g_dis[c0+3] = d3;
    __syncthreads();
    // pass 2: CSR fill with smem position counters
#pragma unroll 4
    for (int e = tid; e < EE; e += 1024) {
        int sN = ei[e];
        int d  = ei[EE + e];
        float w = ew[e];
        int slot = atomicAdd(&s_cnt[d], 1);
        g_srcS[slot] = sN;
        g_nrmS[slot] = s_deg[sN] * w * s_deg[d];
    }
}

// ---------------- 3: aggregate (gather, 1 batch per block) + stats1 ----------
// grid (CC, BB), 256 threads. acc = 1 float4; 4-edge unroll -> 4 indep LDG.128.
__global__ void k_agg(const float* __restrict__ gcnb) {
    __shared__ int    s_src[64];
    __shared__ float  s_nrm[64];
    __shared__ float4 sP[64];
    __shared__ float4 sQ[64];
    int tid = threadIdx.x;
    int c = blockIdx.x;
    int b = blockIdx.y;
    int off = tid * 4;
    float ds = g_dis[c];
    float d2 = ds * ds;
    const float* src_base = g_buf0 + (size_t)b * CC * NSEG;
    float4 v0 = *(const float4*)&src_base[(size_t)c * NSEG + off];
    float4 acc = make_float4(v0.x * d2, v0.y * d2, v0.z * d2, v0.w * d2);
    int beg = g_off[c], end = g_off[c + 1];
    for (int j0 = beg; j0 < end; j0 += 64) {
        int n = min(64, end - j0);
        __syncthreads();
        if (tid < n) {
            s_src[tid] = g_srcS[j0 + tid];
            s_nrm[tid] = g_nrmS[j0 + tid];
        }
        __syncthreads();
        int j = 0;
        for (; j + 4 <= n; j += 4) {
            float4 v[4];
            float nv[4];
#pragma unroll
            for (int e = 0; e < 4; ++e) {
                v[e] = *(const float4*)&src_base[(size_t)s_src[j + e] * NSEG + off];
                nv[e] = s_nrm[j + e];
            }
#pragma unroll
            for (int e = 0; e < 4; ++e) {
                acc.x += v[e].x * nv[e]; acc.y += v[e].y * nv[e];
                acc.z += v[e].z * nv[e]; acc.w += v[e].w * nv[e];
            }
        }
        for (; j < n; ++j) {
            float4 v = *(const float4*)&src_base[(size_t)s_src[j] * NSEG + off];
            float n0 = s_nrm[j];
            acc.x += v.x * n0; acc.y += v.y * n0;
            acc.z += v.z * n0; acc.w += v.w * n0;
        }
    }
    int g0 = off & 31;
    float4 bias = *(const float4*)&gcnb[g0];
    acc.x += bias.x; acc.y += bias.y; acc.z += bias.z; acc.w += bias.w;
    *(float4*)&g_buf1[((size_t)b * CC + c) * NSEG + off] = acc;
    // stats: lanes l, l^8, l^16 share g-quad
    float4 p = acc;
    float4 q = make_float4(p.x*p.x, p.y*p.y, p.z*p.z, p.w*p.w);
#pragma unroll
    for (int m = 8; m <= 16; m <<= 1) {
        p.x += __shfl_xor_sync(0xffffffff, p.x, m);
        p.y += __shfl_xor_sync(0xffffffff, p.y, m);
        p.z += __shfl_xor_sync(0xffffffff, p.z, m);
        p.w += __shfl_xor_sync(0xffffffff, p.w, m);
        q.x += __shfl_xor_sync(0xffffffff, q.x, m);
        q.y += __shfl_xor_sync(0xffffffff, q.y, m);
        q.z += __shfl_xor_sync(0xffffffff, q.z, m);
        q.w += __shfl_xor_sync(0xffffffff, q.w, m);
    }
    int warp = tid >> 5, lane = tid & 31;
    if (lane < 8) { sP[warp * 8 + lane] = p; sQ[warp * 8 + lane] = q; }
    __syncthreads();
    if (tid < 8) {
        float4 tp = sP[tid], tq = sQ[tid];
#pragma unroll
        for (int w = 1; w < 8; ++w) {
            float4 ap = sP[w * 8 + tid], aq = sQ[w * 8 + tid];
            tp.x += ap.x; tp.y += ap.y; tp.z += ap.z; tp.w += ap.w;
            tq.x += aq.x; tq.y += aq.y; tq.z += aq.z; tq.w += aq.w;
        }
        int base = b * 32 + tid * 4;
        atomicAdd(&g_s1[base + 0], tp.x); atomicAdd(&g_s1[base + 1], tp.y);
        atomicAdd(&g_s1[base + 2], tp.z); atomicAdd(&g_s1[base + 3], tp.w);
        atomicAdd(&g_q1[base + 0], tq.x); atomicAdd(&g_q1[base + 1], tq.y);
        atomicAdd(&g_q1[base + 2], tq.z); atomicAdd(&g_q1[base + 3], tq.w);
    }
}

// ---------------- 4: fused IN1+ReLU + temporal conv (1xK) + bias + stats2 ----
// mu1/rs1 computed inline from g_s1/g_q1 (k_fin fused away).
__global__ void k_conv(const float* __restrict__ cw, const float* __restrict__ cb) {
    extern __shared__ char dsm[];
    float* ws = (float*)dsm;
    unsigned long long* zd = (unsigned long long*)(dsm + KK * 1024 * 4);
    int tid = threadIdx.x;
    int bc4 = blockIdx.x;                 // BB*CC/4
    int b = bc4 >> 10;
    int cquad = bc4 & 1023;
    int tile = tid >> 6;
    int r = tid & 63;
    int c = cquad * 4 + tile;

    for (int idx = tid; idx < KK * 1024; idx += 256) {
        int k = idx >> 10;
        int rem = idx & 1023;
        int i = rem >> 5, o = rem & 31;
        ws[idx] = cw[(o * 32 + i) * KK + k];
    }

    size_t base = ((size_t)b * CC + c) * NSEG;
    {
        int g = r & 31;
        float s = g_s1[b * 32 + g], qq = g_q1[b * 32 + g];
        float mu = s * INVN;
        float rs = rsqrtf(qq * INVN - mu * mu + 1e-5f);
        unsigned long long* zt = zd + tile * 1280;
        for (int idx = r; idx < 1280; idx += 64) {
            int row = idx >> 5;
            float v = 0.f;
            if (row >= 4 && row < 36) {
                float h = g_buf1[base + (row - 4) * 32 + (idx & 31)];
                v = fmaxf(0.f, (h - mu) * rs);
            }
            zt[idx] = pack2(v, v);
        }
    }
    __syncthreads();

    int o0 = (r & 7) * 4;
    int tb = (r >> 3) * 4;
    float b0 = cb[o0], b1 = cb[o0 + 1], b2 = cb[o0 + 2], b3 = cb[o0 + 3];
    unsigned long long acc[4][2];
#pragma unroll
    for (int t = 0; t < 4; ++t) { acc[t][0] = pack2(b0, b1); acc[t][1] = pack2(b2, b3); }

    const unsigned long long* zt = zd + tile * 1280;
#pragma unroll 1
    for (int k = 0; k < KK; ++k) {
        const float* wk = ws + k * 1024 + o0;
        const unsigned long long* zr = zt + (tb + k) * 32;
#pragma unroll
        for (int i = 0; i < 32; ++i) {
            ulonglong2 w2 = *(const ulonglong2*)(wk + i * 32);
            unsigned long long z0 = zr[i];
            unsigned long long z1 = zr[32 + i];
            unsigned long long z2 = zr[64 + i];
            unsigned long long z3 = zr[96 + i];
            acc[0][0] = fma2(z0, w2.x, acc[0][0]); acc[0][1] = fma2(z0, w2.y, acc[0][1]);
            acc[1][0] = fma2(z1, w2.x, acc[1][0]); acc[1][1] = fma2(z1, w2.y, acc[1][1]);
            acc[2][0] = fma2(z2, w2.x, acc[2][0]); acc[2][1] = fma2(z2, w2.y, acc[2][1]);
            acc[3][0] = fma2(z3, w2.x, acc[3][0]); acc[3][1] = fma2(z3, w2.y, acc[3][1]);
        }
    }

    float av[4][4];
    float4 p4 = make_float4(0.f, 0.f, 0.f, 0.f);
    float4 q4 = make_float4(0.f, 0.f, 0.f, 0.f);
#pragma unroll
    for (int t = 0; t < 4; ++t) {
        unpack2(acc[t][0], av[t][0], av[t][1]);
        unpack2(acc[t][1], av[t][2], av[t][3]);
        p4.x += av[t][0]; p4.y += av[t][1]; p4.z += av[t][2]; p4.w += av[t][3];
        q4.x += av[t][0]*av[t][0]; q4.y += av[t][1]*av[t][1];
        q4.z += av[t][2]*av[t][2]; q4.w += av[t][3]*av[t][3];
        float4 st = make_float4(av[t][0], av[t][1], av[t][2], av[t][3]);
        *(float4*)&g_buf1[base + (size_t)(tb + t) * 32 + o0] = st;
    }

#pragma unroll
    for (int m = 8; m <= 16; m <<= 1) {
        p4.x += __shfl_xor_sync(0xffffffff, p4.x, m);
        p4.y += __shfl_xor_sync(0xffffffff, p4.y, m);
        p4.z += __shfl_xor_sync(0xffffffff, p4.z, m);
        p4.w += __shfl_xor_sync(0xffffffff, p4.w, m);
        q4.x += __shfl_xor_sync(0xffffffff, q4.x, m);
        q4.y += __shfl_xor_sync(0xffffffff, q4.y, m);
        q4.z += __shfl_xor_sync(0xffffffff, q4.z, m);
        q4.w += __shfl_xor_sync(0xffffffff, q4.w, m);
    }
    __syncthreads();                       // all reads of zt done
    float4* sP = (float4*)zd;
    float4* sQ = sP + 64;
    int warp = tid >> 5, lane = tid & 31;
    if (lane < 8) { sP[warp * 8 + lane] = p4; sQ[warp * 8 + lane] = q4; }
    __syncthreads();
    if (tid < 8) {
        float4 tp = sP[tid], tq = sQ[tid];
#pragma unroll
        for (int w = 1; w < 8; ++w) {
            float4 ap = sP[w * 8 + tid], aq = sQ[w * 8 + tid];
            tp.x += ap.x; tp.y += ap.y; tp.z += ap.z; tp.w += ap.w;
            tq.x += aq.x; tq.y += aq.y; tq.z += aq.z; tq.w += aq.w;
        }
        int basep = b * 32 + tid * 4;
        atomicAdd(&g_s2[basep + 0], tp.x); atomicAdd(&g_s2[basep + 1], tp.y);
        atomicAdd(&g_s2[basep + 2], tp.z); atomicAdd(&g_s2[basep + 3], tp.w);
        atomicAdd(&g_q2[basep + 0], tq.x); atomicAdd(&g_q2[basep + 1], tq.y);
        atomicAdd(&g_q2[basep + 2], tq.z); atomicAdd(&g_q2[basep + 3], tq.w);
    }
}

// ---------------- 5: IN2 + ReLU + residual + ReLU + transpose ----------------
// mu2/rs2 computed inline from g_s2/g_q2 (k_fin fused away).
__global__ void k_final(const float* __restrict__ x, float* __restrict__ out) {
    __shared__ float sy[32 * 33];
    int tid = threadIdx.x;
    int bc = blockIdx.x;
    int b = bc >> 12, c = bc & (CC - 1);
    size_t base = ((size_t)b * CC + c) * NSEG;
    int t = tid >> 3, o0 = (tid & 7) * 4;
    float4 v = *(const float4*)&g_buf1[base + (size_t)tid * 4];
    float4 s4 = *(const float4*)&g_s2[b * 32 + o0];
    float4 q4 = *(const float4*)&g_q2[b * 32 + o0];
    float4 mu, rs;
    mu.x = s4.x * INVN; rs.x = rsqrtf(q4.x * INVN - mu.x * mu.x + 1e-5f);
    mu.y = s4.y * INVN; rs.y = rsqrtf(q4.y * INVN - mu.y * mu.y + 1e-5f);
    mu.z = s4.z * INVN; rs.z = rsqrtf(q4.z * INVN - mu.z * mu.z + 1e-5f);
    mu.w = s4.w * INVN; rs.w = rsqrtf(q4.w * INVN - mu.w * mu.w + 1e-5f);
    sy[t * 33 + o0 + 0] = fmaxf(0.f, (v.x - mu.x) * rs.x);
    sy[t * 33 + o0 + 1] = fmaxf(0.f, (v.y - mu.y) * rs.y);
    sy[t * 33 + o0 + 2] = fmaxf(0.f, (v.z - mu.z) * rs.z);
    sy[t * 33 + o0 + 3] = fmaxf(0.f, (v.w - mu.w) * rs.w);
    __syncthreads();
    int f = tid >> 3, t0 = (tid & 7) * 4;
    size_t xi = (((size_t)b * FF + f) * CC + c) * TT + t0;
    float4 xv = *(const float4*)&x[xi];
    float4 o;
    o.x = fmaxf(0.f, sy[(t0 + 0) * 33 + f] + xv.x);
    o.y = fmaxf(0.f, sy[(t0 + 1) * 33 + f] + xv.y);
    o.z = fmaxf(0.f, sy[(t0 + 2) * 33 + f] + xv.z);
    o.w = fmaxf(0.f, sy[(t0 + 3) * 33 + f] + xv.w);
    *(float4*)&out[xi] = o;
}

// ---------------- launch ----------------
extern "C" void kernel_launch(void* const* d_in, const int* in_sizes, int n_in,
                              void* d_out, int out_size) {
    const float* x    = (const float*)d_in[0];
    const int*   ei   = (const int*)d_in[1];
    const float* ew   = (const float*)d_in[2];
    const float* W    = (const float*)d_in[3];
    const float* gcnb = (const float*)d_in[4];
    const float* cw   = (const float*)d_in[5];
    const float* cb   = (const float*)d_in[6];
    float* out = (float*)d_out;

    const int conv_smem = KK * 1024 * 4 + 4 * 1280 * 8;   // 77824
    cudaFuncSetAttribute(k_conv, cudaFuncAttributeMaxDynamicSharedMemorySize, conv_smem);

    // 5 launches; k_conv is the 4th => lands in ncu's captured slot next round.
    k_xlin <<<BB * CC, 256>>>(x, W);
    k_setup<<<1, 1024>>>(ei, ew);
    k_agg  <<<dim3(CC, BB), 256>>>(gcnb);
    k_conv <<<BB * CC / 4, 256, conv_smem>>>(cw, cb);
    k_final<<<BB * CC, 256>>>(x, out);
}

// round 11
// speedup vs baseline: 1.1454x; 1.1454x over previous
#include <cuda_runtime.h>

#define BB 4
#define FF 32
#define CC 4096
#define TT 32
#define EE 65536
#define KK 9
#define NSEG 1024               // T*F floats per (b,c) tile
#define NTOT (BB*FF*CC*TT)      // 16777216
#define INVN (1.0f / 131072.0f) // 1/(CC*TT)

// ---------------- scratch (device globals; no allocs allowed) ----------------
__device__ float g_dis[CC];
__device__ int   g_off[CC + 1];
__device__ int   g_srcS[EE];     // CSR-sorted source node per slot
__device__ float g_nrmS[EE];     // CSR-sorted edge norm per slot
__device__ float g_buf0[NTOT];   // x_lin
__device__ float g_buf1[NTOT];   // h1 -> overwritten in-place by conv out
__device__ float g_s1[BB*FF], g_q1[BB*FF], g_s2[BB*FF], g_q2[BB*FF];

// ---------------- packed f32x2 helpers ----------------
__device__ __forceinline__ unsigned long long pack2(float x, float y) {
    unsigned long long r;
    asm("mov.b64 %0, {%1,%2};" : "=l"(r) : "f"(x), "f"(y));
    return r;
}
__device__ __forceinline__ void unpack2(unsigned long long v, float& x, float& y) {
    asm("mov.b64 {%0,%1}, %2;" : "=f"(x), "=f"(y) : "l"(v));
}
__device__ __forceinline__ unsigned long long fma2(unsigned long long a,
                                                   unsigned long long b,
                                                   unsigned long long c) {
    unsigned long long d;
    asm("fma.rn.f32x2 %0, %1, %2, %3;" : "=l"(d) : "l"(a), "l"(b), "l"(c));
    return d;
}

// ---------------- 1: x_lin[b,c,t,g] = sum_f x[b,f,c,t] * W[f,g] --------------
__global__ void k_xlin(const float* __restrict__ x, const float* __restrict__ W) {
    __shared__ float xs[32 * 33];
    __shared__ float ws[1024];          // [f][g]
    int tid = threadIdx.x;
    int bc = blockIdx.x;
    int b = bc >> 12, c = bc & (CC - 1);
    ((float4*)ws)[tid] = ((const float4*)W)[tid];
    int lf = tid >> 3, lt0 = (tid & 7) * 4;
    float4 xv = *(const float4*)&x[(((size_t)b * FF + lf) * CC + c) * TT + lt0];
    xs[(lt0 + 0) * 33 + lf] = xv.x;
    xs[(lt0 + 1) * 33 + lf] = xv.y;
    xs[(lt0 + 2) * 33 + lf] = xv.z;
    xs[(lt0 + 3) * 33 + lf] = xv.w;
    __syncthreads();
    int t = tid >> 3, g0 = (tid & 7) * 4;
    unsigned long long a0 = pack2(0.f, 0.f), a1 = pack2(0.f, 0.f);
#pragma unroll
    for (int f = 0; f < 32; ++f) {
        float z = xs[t * 33 + f];
        unsigned long long zz = pack2(z, z);
        ulonglong2 w2 = *(const ulonglong2*)&ws[f * 32 + g0];
        a0 = fma2(zz, w2.x, a0);
        a1 = fma2(zz, w2.y, a1);
    }
    float4 o;
    unpack2(a0, o.x, o.y);
    unpack2(a1, o.z, o.w);
    *(float4*)&g_buf0[((size_t)b * CC + c) * NSEG + (size_t)tid * 4] = o;
}

// ---------------- 2: fused prep + degree + scan + CSR fill -------------------
__global__ void k_setup(const int* __restrict__ ei, const float* __restrict__ ew) {
    __shared__ float s_deg[CC];         // deg, then overwritten with dis
    __shared__ int   s_cnt[CC];         // counts, then running CSR positions
    __shared__ int   s_scan[1024];
    int tid = threadIdx.x;
#pragma unroll
    for (int i = tid; i < CC; i += 1024) { s_deg[i] = 1.0f; s_cnt[i] = 0; }
    if (tid < BB * FF) {
        g_s1[tid] = 0.f; g_q1[tid] = 0.f; g_s2[tid] = 0.f; g_q2[tid] = 0.f;
    }
    __syncthreads();
#pragma unroll 4
    for (int e = tid; e < EE; e += 1024) {
        int d = ei[EE + e];
        atomicAdd(&s_deg[d], ew[e]);
        atomicAdd(&s_cnt[d], 1);
    }
    __syncthreads();
    int c0 = tid * 4;
    int l0 = s_cnt[c0], l1 = s_cnt[c0+1], l2 = s_cnt[c0+2], l3 = s_cnt[c0+3];
    int tot = l0 + l1 + l2 + l3;
    s_scan[tid] = tot;
    __syncthreads();
    for (int d = 1; d < 1024; d <<= 1) {
        int v = 0;
        if (tid >= d) v = s_scan[tid - d];
        __syncthreads();
        if (tid >= d) s_scan[tid] += v;
        __syncthreads();
    }
    int excl = s_scan[tid] - tot;
    g_off[c0]   = excl;
    g_off[c0+1] = excl + l0;
    g_off[c0+2] = excl + l0 + l1;
    g_off[c0+3] = excl + l0 + l1 + l2;
    if (tid == 1023) g_off[CC] = s_scan[1023];
    s_cnt[c0]   = excl;
    s_cnt[c0+1] = excl + l0;
    s_cnt[c0+2] = excl + l0 + l1;
    s_cnt[c0+3] = excl + l0 + l1 + l2;
    float d0 = rsqrtf(s_deg[c0]),   d1 = rsqrtf(s_deg[c0+1]);
    float d2 = rsqrtf(s_deg[c0+2]), d3 = rsqrtf(s_deg[c0+3]);
    s_deg[c0] = d0; s_deg[c0+1] = d1; s_deg[c0+2] = d2; s_deg[c0+3] = d3;
    g_dis[c0] = d0; g_dis[c0+1] = d1; g_dis[c0+2] = d2; g_dis[c0+3] = d3;
    __syncthreads();
#pragma unroll 4
    for (int e = tid; e < EE; e += 1024) {
        int sN = ei[e];
        int d  = ei[EE + e];
        float w = ew[e];
        int slot = atomicAdd(&s_cnt[d], 1);
        g_srcS[slot] = sN;
        g_nrmS[slot] = s_deg[sN] * w * s_deg[d];
    }
}

// ---------------- 3: aggregate (gather, ALL 4 batches per block) + stats1 ----
// REVERT to the measured-200us form: 256 threads, 1 block per node c,
// 2-edge unroll -> 8 independent LDG.128 per step.
__global__ void k_agg(const float* __restrict__ gcnb) {
    __shared__ int    s_src[64];
    __shared__ float  s_nrm[64];
    __shared__ float4 sP[64];
    __shared__ float4 sQ[64];
    int tid = threadIdx.x;
    int c = blockIdx.x;
    int off = tid * 4;
    float ds = g_dis[c];
    float d2 = ds * ds;
    float4 acc[BB];
#pragma unroll
    for (int b = 0; b < BB; ++b) {
        float4 v = *(const float4*)&g_buf0[((size_t)b * CC + c) * NSEG + off];
        acc[b] = make_float4(v.x * d2, v.y * d2, v.z * d2, v.w * d2);
    }
    int beg = g_off[c], end = g_off[c + 1];
    for (int j0 = beg; j0 < end; j0 += 64) {
        int n = min(64, end - j0);
        __syncthreads();
        if (tid < n) {
            s_src[tid] = g_srcS[j0 + tid];
            s_nrm[tid] = g_nrmS[j0 + tid];
        }
        __syncthreads();
        int j = 0;
        for (; j + 2 <= n; j += 2) {
            int s0 = s_src[j], s1 = s_src[j + 1];
            float n0 = s_nrm[j], n1 = s_nrm[j + 1];
            float4 v[2 * BB];
#pragma unroll
            for (int b = 0; b < BB; ++b) {
                v[b]      = *(const float4*)&g_buf0[((size_t)b * CC + s0) * NSEG + off];
                v[BB + b] = *(const float4*)&g_buf0[((size_t)b * CC + s1) * NSEG + off];
            }
#pragma unroll
            for (int b = 0; b < BB; ++b) {
                acc[b].x += v[b].x * n0; acc[b].y += v[b].y * n0;
                acc[b].z += v[b].z * n0; acc[b].w += v[b].w * n0;
                acc[b].x += v[BB+b].x * n1; acc[b].y += v[BB+b].y * n1;
                acc[b].z += v[BB+b].z * n1; acc[b].w += v[BB+b].w * n1;
            }
        }
        if (j < n) {
            int s0 = s_src[j];
            float n0 = s_nrm[j];
#pragma unroll
            for (int b = 0; b < BB; ++b) {
                float4 v = *(const float4*)&g_buf0[((size_t)b * CC + s0) * NSEG + off];
                acc[b].x += v.x * n0; acc[b].y += v.y * n0;
                acc[b].z += v.z * n0; acc[b].w += v.w * n0;
            }
        }
    }
    int g0 = off & 31;
    float4 bias = *(const float4*)&gcnb[g0];
    int warp = tid >> 5, lane = tid & 31;
#pragma unroll
    for (int b = 0; b < BB; ++b) {
        acc[b].x += bias.x; acc[b].y += bias.y;
        acc[b].z += bias.z; acc[b].w += bias.w;
        *(float4*)&g_buf1[((size_t)b * CC + c) * NSEG + off] = acc[b];
        float4 p = acc[b];
        float4 q = make_float4(p.x*p.x, p.y*p.y, p.z*p.z, p.w*p.w);
#pragma unroll
        for (int m = 8; m <= 16; m <<= 1) {
            p.x += __shfl_xor_sync(0xffffffff, p.x, m);
            p.y += __shfl_xor_sync(0xffffffff, p.y, m);
            p.z += __shfl_xor_sync(0xffffffff, p.z, m);
            p.w += __shfl_xor_sync(0xffffffff, p.w, m);
            q.x += __shfl_xor_sync(0xffffffff, q.x, m);
            q.y += __shfl_xor_sync(0xffffffff, q.y, m);
            q.z += __shfl_xor_sync(0xffffffff, q.z, m);
            q.w += __shfl_xor_sync(0xffffffff, q.w, m);
        }
        if (lane < 8) { sP[warp * 8 + lane] = p; sQ[warp * 8 + lane] = q; }
        __syncthreads();
        if (tid < 8) {
            float4 tp = sP[tid], tq = sQ[tid];
#pragma unroll
            for (int w = 1; w < 8; ++w) {
                float4 ap = sP[w * 8 + tid], aq = sQ[w * 8 + tid];
                tp.x += ap.x; tp.y += ap.y; tp.z += ap.z; tp.w += ap.w;
                tq.x += aq.x; tq.y += aq.y; tq.z += aq.z; tq.w += aq.w;
            }
            int base = b * 32 + tid * 4;
            atomicAdd(&g_s1[base + 0], tp.x); atomicAdd(&g_s1[base + 1], tp.y);
            atomicAdd(&g_s1[base + 2], tp.z); atomicAdd(&g_s1[base + 3], tp.w);
            atomicAdd(&g_q1[base + 0], tq.x); atomicAdd(&g_q1[base + 1], tq.y);
            atomicAdd(&g_q1[base + 2], tq.z); atomicAdd(&g_q1[base + 3], tq.w);
        }
        __syncthreads();
    }
}

// ---------------- 4: fused IN1+ReLU + temporal conv + bias + stats2 ----------
// 128 threads = 4 tiles of 32 threads; thread computes 4t x 8o.
// Per i-step: 2 LDS.128 (weights) + 4 LDS.64 (z splats) + 16 fma2 = 2 B/MAC.
__global__ void k_conv(const float* __restrict__ cw, const float* __restrict__ cb) {
    extern __shared__ char dsm[];
    float* ws = (float*)dsm;                                   // [k][i][o] 36864B
    unsigned long long* zd = (unsigned long long*)(dsm + KK * 1024 * 4);  // 4x1280 ull
    int tid = threadIdx.x;
    int bc4 = blockIdx.x;                 // BB*CC/4 blocks
    int b = bc4 >> 10;
    int cquad = bc4 & 1023;
    int tile = tid >> 5;
    int r = tid & 31;
    int c = cquad * 4 + tile;

    for (int idx = tid; idx < KK * 1024; idx += 128) {
        int k = idx >> 10;
        int rem = idx & 1023;
        int i = rem >> 5, o = rem & 31;
        ws[idx] = cw[(o * 32 + i) * KK + k];
    }

    size_t base = ((size_t)b * CC + c) * NSEG;
    {
        float s = g_s1[b * 32 + r], qq = g_q1[b * 32 + r];
        float mu = s * INVN;
        float rs = rsqrtf(qq * INVN - mu * mu + 1e-5f);
        unsigned long long* zt = zd + tile * 1280;
#pragma unroll
        for (int it = 0; it < 40; ++it) {
            int row = it;
            float v = 0.f;
            if (row >= 4 && row < 36) {
                float h = g_buf1[base + (row - 4) * 32 + r];
                v = fmaxf(0.f, (h - mu) * rs);
            }
            zt[row * 32 + r] = pack2(v, v);
        }
    }
    __syncthreads();

    int o0 = (r & 3) * 8;                 // 4 o-groups of 8
    int tb = (r >> 2) * 4;                // 8 t-blocks of 4
    ulonglong2 cb2a = *(const ulonglong2*)&cb[o0];      // {b0,b1},{b2,b3}
    ulonglong2 cb2b = *(const ulonglong2*)&cb[o0 + 4];  // {b4,b5},{b6,b7}
    unsigned long long acc[4][4];
#pragma unroll
    for (int t = 0; t < 4; ++t) {
        acc[t][0] = cb2a.x; acc[t][1] = cb2a.y;
        acc[t][2] = cb2b.x; acc[t][3] = cb2b.y;
    }

    const unsigned long long* zt = zd + tile * 1280;
#pragma unroll 1
    for (int k = 0; k < KK; ++k) {
        const float* wk = ws + k * 1024 + o0;
        const unsigned long long* zr = zt + (tb + k) * 32;
#pragma unroll
        for (int i = 0; i < 32; ++i) {
            ulonglong2 wa = *(const ulonglong2*)(wk + i * 32);
            ulonglong2 wb = *(const ulonglong2*)(wk + i * 32 + 4);
            unsigned long long z0 = zr[i];
            unsigned long long z1 = zr[32 + i];
            unsigned long long z2 = zr[64 + i];
            unsigned long long z3 = zr[96 + i];
            acc[0][0] = fma2(z0, wa.x, acc[0][0]); acc[0][1] = fma2(z0, wa.y, acc[0][1]);
            acc[0][2] = fma2(z0, wb.x, acc[0][2]); acc[0][3] = fma2(z0, wb.y, acc[0][3]);
            acc[1][0] = fma2(z1, wa.x, acc[1][0]); acc[1][1] = fma2(z1, wa.y, acc[1][1]);
            acc[1][2] = fma2(z1, wb.x, acc[1][2]); acc[1][3] = fma2(z1, wb.y, acc[1][3]);
            acc[2][0] = fma2(z2, wa.x, acc[2][0]); acc[2][1] = fma2(z2, wa.y, acc[2][1]);
            acc[2][2] = fma2(z2, wb.x, acc[2][2]); acc[2][3] = fma2(z2, wb.y, acc[2][3]);
            acc[3][0] = fma2(z3, wa.x, acc[3][0]); acc[3][1] = fma2(z3, wa.y, acc[3][1]);
            acc[3][2] = fma2(z3, wb.x, acc[3][2]); acc[3][3] = fma2(z3, wb.y, acc[3][3]);
        }
    }

    // unpack, store (in-place), accumulate per-o stats (8 o's per thread)
    float av[8];
    float4 pa = make_float4(0.f,0.f,0.f,0.f), pb = pa, qa = pa, qb = pa;
#pragma unroll
    for (int t = 0; t < 4; ++t) {
        unpack2(acc[t][0], av[0], av[1]);
        unpack2(acc[t][1], av[2], av[3]);
        unpack2(acc[t][2], av[4], av[5]);
        unpack2(acc[t][3], av[6], av[7]);
        pa.x += av[0]; pa.y += av[1]; pa.z += av[2]; pa.w += av[3];
        pb.x += av[4]; pb.y += av[5]; pb.z += av[6]; pb.w += av[7];
        qa.x += av[0]*av[0]; qa.y += av[1]*av[1]; qa.z += av[2]*av[2]; qa.w += av[3]*av[3];
        qb.x += av[4]*av[4]; qb.y += av[5]*av[5]; qb.z += av[6]*av[6]; qb.w += av[7]*av[7];
        *(float4*)&g_buf1[base + (size_t)(tb + t) * 32 + o0]     = make_float4(av[0], av[1], av[2], av[3]);
        *(float4*)&g_buf1[base + (size_t)(tb + t) * 32 + o0 + 4] = make_float4(av[4], av[5], av[6], av[7]);
    }

    // stats2: lanes sharing r&3 (masks 4,8,16) share the same o-group.
#pragma unroll
    for (int m = 4; m <= 16; m <<= 1) {
        pa.x += __shfl_xor_sync(0xffffffff, pa.x, m);
        pa.y += __shfl_xor_sync(0xffffffff, pa.y, m);
        pa.z += __shfl_xor_sync(0xffffffff, pa.z, m);
        pa.w += __shfl_xor_sync(0xffffffff, pa.w, m);
        pb.x += __shfl_xor_sync(0xffffffff, pb.x, m);
        pb.y += __shfl_xor_sync(0xffffffff, pb.y, m);
        pb.z += __shfl_xor_sync(0xffffffff, pb.z, m);
        pb.w += __shfl_xor_sync(0xffffffff, pb.w, m);
        qa.x += __shfl_xor_sync(0xffffffff, qa.x, m);
        qa.y += __shfl_xor_sync(0xffffffff, qa.y, m);
        qa.z += __shfl_xor_sync(0xffffffff, qa.z, m);
        qa.w += __shfl_xor_sync(0xffffffff, qa.w, m);
        qb.x += __shfl_xor_sync(0xffffffff, qb.x, m);
        qb.y += __shfl_xor_sync(0xffffffff, qb.y, m);
        qb.z += __shfl_xor_sync(0xffffffff, qb.z, m);
        qb.w += __shfl_xor_sync(0xffffffff, qb.w, m);
    }
    __syncthreads();                       // all reads of zt done; reuse zd
    float4* sS = (float4*)zd;              // [4 arrays][warp*4+lane]
    if (r < 4) {
        int idx = tile * 4 + r;
        sS[idx] = pa; sS[16 + idx] = pb; sS[32 + idx] = qa; sS[48 + idx] = qb;
    }
    __syncthreads();
    if (tid < 4) {
        float4 tpa = sS[tid], tpb = sS[16 + tid], tqa = sS[32 + tid], tqb = sS[48 + tid];
#pragma unroll
        for (int w = 1; w < 4; ++w) {
            float4 a = sS[w * 4 + tid], bq = sS[16 + w * 4 + tid];
            float4 cq = sS[32 + w * 4 + tid], dq = sS[48 + w * 4 + tid];
            tpa.x += a.x; tpa.y += a.y; tpa.z += a.z; tpa.w += a.w;
            tpb.x += bq.x; tpb.y += bq.y; tpb.z += bq.z; tpb.w += bq.w;
            tqa.x += cq.x; tqa.y += cq.y; tqa.z += cq.z; tqa.w += cq.w;
            tqb.x += dq.x; tqb.y += dq.y; tqb.z += dq.z; tqb.w += dq.w;
        }
        int basep = b * 32 + tid * 8;
        atomicAdd(&g_s2[basep + 0], tpa.x); atomicAdd(&g_s2[basep + 1], tpa.y);
        atomicAdd(&g_s2[basep + 2], tpa.z); atomicAdd(&g_s2[basep + 3], tpa.w);
        atomicAdd(&g_s2[basep + 4], tpb.x); atomicAdd(&g_s2[basep + 5], tpb.y);
        atomicAdd(&g_s2[basep + 6], tpb.z); atomicAdd(&g_s2[basep + 7], tpb.w);
        atomicAdd(&g_q2[basep + 0], tqa.x); atomicAdd(&g_q2[basep + 1], tqa.y);
        atomicAdd(&g_q2[basep + 2], tqa.z); atomicAdd(&g_q2[basep + 3], tqa.w);
        atomicAdd(&g_q2[basep + 4], tqb.x); atomicAdd(&g_q2[basep + 5], tqb.y);
        atomicAdd(&g_q2[basep + 6], tqb.z); atomicAdd(&g_q2[basep + 7], tqb.w);
    }
}

// ---------------- 5: IN2 + ReLU + residual + ReLU + transpose ----------------
__global__ void k_final(const float* __restrict__ x, float* __restrict__ out) {
    __shared__ float sy[32 * 33];
    int tid = threadIdx.x;
    int bc = blockIdx.x;
    int b = bc >> 12, c = bc & (CC - 1);
    size_t base = ((size_t)b * CC + c) * NSEG;
    int t = tid >> 3, o0 = (tid & 7) * 4;
    float4 v = *(const float4*)&g_buf1[base + (size_t)tid * 4];
    float4 s4 = *(const float4*)&g_s2[b * 32 + o0];
    float4 q4 = *(const float4*)&g_q2[b * 32 + o0];
    float4 mu, rs;
    mu.x = s4.x * INVN; rs.x = rsqrtf(q4.x * INVN - mu.x * mu.x + 1e-5f);
    mu.y = s4.y * INVN; rs.y = rsqrtf(q4.y * INVN - mu.y * mu.y + 1e-5f);
    mu.z = s4.z * INVN; rs.z = rsqrtf(q4.z * INVN - mu.z * mu.z + 1e-5f);
    mu.w = s4.w * INVN; rs.w = rsqrtf(q4.w * INVN - mu.w * mu.w + 1e-5f);
    sy[t * 33 + o0 + 0] = fmaxf(0.f, (v.x - mu.x) * rs.x);
    sy[t * 33 + o0 + 1] = fmaxf(0.f, (v.y - mu.y) * rs.y);
    sy[t * 33 + o0 + 2] = fmaxf(0.f, (v.z - mu.z) * rs.z);
    sy[t * 33 + o0 + 3] = fmaxf(0.f, (v.w - mu.w) * rs.w);
    __syncthreads();
    int f = tid >> 3, t0 = (tid & 7) * 4;
    size_t xi = (((size_t)b * FF + f) * CC + c) * TT + t0;
    float4 xv = *(const float4*)&x[xi];
    float4 o;
    o.x = fmaxf(0.f, sy[(t0 + 0) * 33 + f] + xv.x);
    o.y = fmaxf(0.f, sy[(t0 + 1) * 33 + f] + xv.y);
    o.z = fmaxf(0.f, sy[(t0 + 2) * 33 + f] + xv.z);
    o.w = fmaxf(0.f, sy[(t0 + 3) * 33 + f] + xv.w);
    *(float4*)&out[xi] = o;
}

// ---------------- launch ----------------
extern "C" void kernel_launch(void* const* d_in, const int* in_sizes, int n_in,
                              void* d_out, int out_size) {
    const float* x    = (const float*)d_in[0];
    const int*   ei   = (const int*)d_in[1];
    const float* ew   = (const float*)d_in[2];
    const float* W    = (const float*)d_in[3];
    const float* gcnb = (const float*)d_in[4];
    const float* cw   = (const float*)d_in[5];
    const float* cb   = (const float*)d_in[6];
    float* out = (float*)d_out;

    const int conv_smem = KK * 1024 * 4 + 4 * 1280 * 8;   // 77824
    cudaFuncSetAttribute(k_conv, cudaFuncAttributeMaxDynamicSharedMemorySize, conv_smem);

    // 5 launches; k_conv stays 4th => profiled next round.
    k_xlin <<<BB * CC, 256>>>(x, W);
    k_setup<<<1, 1024>>>(ei, ew);
    k_agg  <<<CC, 256>>>(gcnb);
    k_conv <<<BB * CC / 4, 128, conv_smem>>>(cw, cb);
    k_final<<<BB * CC, 256>>>(x, out);
}

// round 12
// speedup vs baseline: 1.5282x; 1.3342x over previous
#include <cuda_runtime.h>

#define BB 4
#define FF 32
#define CC 4096
#define TT 32
#define EE 65536
#define KK 9
#define NSEG 1024               // T*F floats per (b,c) tile
#define NTOT (BB*FF*CC*TT)      // 16777216
#define INVN (1.0f / 131072.0f) // 1/(CC*TT)

// ---------------- scratch (device globals; no allocs allowed) ----------------
__device__ float g_dis[CC];
__device__ int   g_off[CC + 1];
__device__ int   g_srcS[EE];     // CSR-sorted source node per slot
__device__ float g_nrmS[EE];     // CSR-sorted edge norm per slot
__device__ float g_buf0[NTOT];   // x_lin
__device__ float g_buf1[NTOT];   // h1 -> overwritten in-place by conv out
__device__ float g_s1[BB*FF], g_q1[BB*FF], g_s2[BB*FF], g_q2[BB*FF];

// ---------------- packed f32x2 helpers ----------------
__device__ __forceinline__ unsigned long long pack2(float x, float y) {
    unsigned long long r;
    asm("mov.b64 %0, {%1,%2};" : "=l"(r) : "f"(x), "f"(y));
    return r;
}
__device__ __forceinline__ void unpack2(unsigned long long v, float& x, float& y) {
    asm("mov.b64 {%0,%1}, %2;" : "=f"(x), "=f"(y) : "l"(v));
}
__device__ __forceinline__ unsigned long long fma2(unsigned long long a,
                                                   unsigned long long b,
                                                   unsigned long long c) {
    unsigned long long d;
    asm("fma.rn.f32x2 %0, %1, %2, %3;" : "=l"(d) : "l"(a), "l"(b), "l"(c));
    return d;
}

// ---------------- 1: x_lin[b,c,t,g] = sum_f x[b,f,c,t] * W[f,g] --------------
__global__ void k_xlin(const float* __restrict__ x, const float* __restrict__ W) {
    __shared__ float xs[32 * 33];
    __shared__ float ws[1024];          // [f][g]
    int tid = threadIdx.x;
    int bc = blockIdx.x;
    int b = bc >> 12, c = bc & (CC - 1);
    ((float4*)ws)[tid] = ((const float4*)W)[tid];
    int lf = tid >> 3, lt0 = (tid & 7) * 4;
    float4 xv = *(const float4*)&x[(((size_t)b * FF + lf) * CC + c) * TT + lt0];
    xs[(lt0 + 0) * 33 + lf] = xv.x;
    xs[(lt0 + 1) * 33 + lf] = xv.y;
    xs[(lt0 + 2) * 33 + lf] = xv.z;
    xs[(lt0 + 3) * 33 + lf] = xv.w;
    __syncthreads();
    int t = tid >> 3, g0 = (tid & 7) * 4;
    unsigned long long a0 = pack2(0.f, 0.f), a1 = pack2(0.f, 0.f);
#pragma unroll
    for (int f = 0; f < 32; ++f) {
        float z = xs[t * 33 + f];
        unsigned long long zz = pack2(z, z);
        ulonglong2 w2 = *(const ulonglong2*)&ws[f * 32 + g0];
        a0 = fma2(zz, w2.x, a0);
        a1 = fma2(zz, w2.y, a1);
    }
    float4 o;
    unpack2(a0, o.x, o.y);
    unpack2(a1, o.z, o.w);
    *(float4*)&g_buf0[((size_t)b * CC + c) * NSEG + (size_t)tid * 4] = o;
}

// ---------------- 2: fused prep + degree + scan + CSR fill -------------------
__global__ void k_setup(const int* __restrict__ ei, const float* __restrict__ ew) {
    __shared__ float s_deg[CC];
    __shared__ int   s_cnt[CC];
    __shared__ int   s_scan[1024];
    int tid = threadIdx.x;
#pragma unroll
    for (int i = tid; i < CC; i += 1024) { s_deg[i] = 1.0f; s_cnt[i] = 0; }
    if (tid < BB * FF) {
        g_s1[tid] = 0.f; g_q1[tid] = 0.f; g_s2[tid] = 0.f; g_q2[tid] = 0.f;
    }
    __syncthreads();
#pragma unroll 4
    for (int e = tid; e < EE; e += 1024) {
        int d = ei[EE + e];
        atomicAdd(&s_deg[d], ew[e]);
        atomicAdd(&s_cnt[d], 1);
    }
    __syncthreads();
    int c0 = tid * 4;
    int l0 = s_cnt[c0], l1 = s_cnt[c0+1], l2 = s_cnt[c0+2], l3 = s_cnt[c0+3];
    int tot = l0 + l1 + l2 + l3;
    s_scan[tid] = tot;
    __syncthreads();
    for (int d = 1; d < 1024; d <<= 1) {
        int v = 0;
        if (tid >= d) v = s_scan[tid - d];
        __syncthreads();
        if (tid >= d) s_scan[tid] += v;
        __syncthreads();
    }
    int excl = s_scan[tid] - tot;
    g_off[c0]   = excl;
    g_off[c0+1] = excl + l0;
    g_off[c0+2] = excl + l0 + l1;
    g_off[c0+3] = excl + l0 + l1 + l2;
    if (tid == 1023) g_off[CC] = s_scan[1023];
    s_cnt[c0]   = excl;
    s_cnt[c0+1] = excl + l0;
    s_cnt[c0+2] = excl + l0 + l1;
    s_cnt[c0+3] = excl + l0 + l1 + l2;
    float d0 = rsqrtf(s_deg[c0]),   d1 = rsqrtf(s_deg[c0+1]);
    float d2 = rsqrtf(s_deg[c0+2]), d3 = rsqrtf(s_deg[c0+3]);
    s_deg[c0] = d0; s_deg[c0+1] = d1; s_deg[c0+2] = d2; s_deg[c0+3] = d3;
    g_dis[c0] = d0; g_dis[c0+1] = d1; g_dis[c0+2] = d2; g_dis[c0+3] = d3;
    __syncthreads();
#pragma unroll 4
    for (int e = tid; e < EE; e += 1024) {
        int sN = ei[e];
        int d  = ei[EE + e];
        float w = ew[e];
        int slot = atomicAdd(&s_cnt[d], 1);
        g_srcS[slot] = sN;
        g_nrmS[slot] = s_deg[sN] * w * s_deg[d];
    }
}

// ---------------- 3: aggregate (gather, ALL 4 batches per block) + stats1 ----
__global__ void k_agg(const float* __restrict__ gcnb) {
    __shared__ int    s_src[64];
    __shared__ float  s_nrm[64];
    __shared__ float4 sP[64];
    __shared__ float4 sQ[64];
    int tid = threadIdx.x;
    int c = blockIdx.x;
    int off = tid * 4;
    float ds = g_dis[c];
    float d2 = ds * ds;
    float4 acc[BB];
#pragma unroll
    for (int b = 0; b < BB; ++b) {
        float4 v = *(const float4*)&g_buf0[((size_t)b * CC + c) * NSEG + off];
        acc[b] = make_float4(v.x * d2, v.y * d2, v.z * d2, v.w * d2);
    }
    int beg = g_off[c], end = g_off[c + 1];
    for (int j0 = beg; j0 < end; j0 += 64) {
        int n = min(64, end - j0);
        __syncthreads();
        if (tid < n) {
            s_src[tid] = g_srcS[j0 + tid];
            s_nrm[tid] = g_nrmS[j0 + tid];
        }
        __syncthreads();
        int j = 0;
        for (; j + 2 <= n; j += 2) {
            int s0 = s_src[j], s1 = s_src[j + 1];
            float n0 = s_nrm[j], n1 = s_nrm[j + 1];
            float4 v[2 * BB];
#pragma unroll
            for (int b = 0; b < BB; ++b) {
                v[b]      = *(const float4*)&g_buf0[((size_t)b * CC + s0) * NSEG + off];
                v[BB + b] = *(const float4*)&g_buf0[((size_t)b * CC + s1) * NSEG + off];
            }
#pragma unroll
            for (int b = 0; b < BB; ++b) {
                acc[b].x += v[b].x * n0; acc[b].y += v[b].y * n0;
                acc[b].z += v[b].z * n0; acc[b].w += v[b].w * n0;
                acc[b].x += v[BB+b].x * n1; acc[b].y += v[BB+b].y * n1;
                acc[b].z += v[BB+b].z * n1; acc[b].w += v[BB+b].w * n1;
            }
        }
        if (j < n) {
            int s0 = s_src[j];
            float n0 = s_nrm[j];
#pragma unroll
            for (int b = 0; b < BB; ++b) {
                float4 v = *(const float4*)&g_buf0[((size_t)b * CC + s0) * NSEG + off];
                acc[b].x += v.x * n0; acc[b].y += v.y * n0;
                acc[b].z += v.z * n0; acc[b].w += v.w * n0;
            }
        }
    }
    int g0 = off & 31;
    float4 bias = *(const float4*)&gcnb[g0];
    int warp = tid >> 5, lane = tid & 31;
#pragma unroll
    for (int b = 0; b < BB; ++b) {
        acc[b].x += bias.x; acc[b].y += bias.y;
        acc[b].z += bias.z; acc[b].w += bias.w;
        *(float4*)&g_buf1[((size_t)b * CC + c) * NSEG + off] = acc[b];
        float4 p = acc[b];
        float4 q = make_float4(p.x*p.x, p.y*p.y, p.z*p.z, p.w*p.w);
#pragma unroll
        for (int m = 8; m <= 16; m <<= 1) {
            p.x += __shfl_xor_sync(0xffffffff, p.x, m);
            p.y += __shfl_xor_sync(0xffffffff, p.y, m);
            p.z += __shfl_xor_sync(0xffffffff, p.z, m);
            p.w += __shfl_xor_sync(0xffffffff, p.w, m);
            q.x += __shfl_xor_sync(0xffffffff, q.x, m);
            q.y += __shfl_xor_sync(0xffffffff, q.y, m);
            q.z += __shfl_xor_sync(0xffffffff, q.z, m);
            q.w += __shfl_xor_sync(0xffffffff, q.w, m);
        }
        if (lane < 8) { sP[warp * 8 + lane] = p; sQ[warp * 8 + lane] = q; }
        __syncthreads();
        if (tid < 8) {
            float4 tp = sP[tid], tq = sQ[tid];
#pragma unroll
            for (int w = 1; w < 8; ++w) {
                float4 ap = sP[w * 8 + tid], aq = sQ[w * 8 + tid];
                tp.x += ap.x; tp.y += ap.y; tp.z += ap.z; tp.w += ap.w;
                tq.x += aq.x; tq.y += aq.y; tq.z += aq.z; tq.w += aq.w;
            }
            int base = b * 32 + tid * 4;
            atomicAdd(&g_s1[base + 0], tp.x); atomicAdd(&g_s1[base + 1], tp.y);
            atomicAdd(&g_s1[base + 2], tp.z); atomicAdd(&g_s1[base + 3], tp.w);
            atomicAdd(&g_q1[base + 0], tq.x); atomicAdd(&g_q1[base + 1], tq.y);
            atomicAdd(&g_q1[base + 2], tq.z); atomicAdd(&g_q1[base + 3], tq.w);
        }
        __syncthreads();
    }
}

// ---------------- 4: fused IN1+ReLU + temporal conv + bias + stats2 ----------
// 256 threads = 16 tiles of 16 threads; thread computes 8t x 8o.
// i-major loop: per i, 16 z-splat LDS.64 (128B) amortized over 9 k-taps
// -> 416 B requested per 576 MACs = 0.72 B/MAC.
__global__ void __launch_bounds__(256, 1)
k_conv(const float* __restrict__ cw, const float* __restrict__ cb) {
    extern __shared__ char dsm[];
    float* ws = (float*)dsm;                                   // [k][i][o] 36864B
    unsigned long long* zd = (unsigned long long*)(dsm + KK * 1024 * 4); // 16x1280
    int tid = threadIdx.x;
    int blk = blockIdx.x;                 // BB*CC/16
    int b = blk >> 8;
    int c16 = blk & 255;
    int tile = tid >> 4;
    int r = tid & 15;
    int c = c16 * 16 + tile;

    for (int idx = tid; idx < KK * 1024; idx += 256) {
        int k = idx >> 10;
        int rem = idx & 1023;
        int i = rem >> 5, o = rem & 31;
        ws[idx] = cw[(o * 32 + i) * KK + k];
    }

    size_t base = ((size_t)b * CC + c) * NSEG;
    {
        // thread fills columns r and r+16 of its tile, all 40 rows
        float s0 = g_s1[b * 32 + r],      qq0 = g_q1[b * 32 + r];
        float s1 = g_s1[b * 32 + r + 16], qq1 = g_q1[b * 32 + r + 16];
        float mu0 = s0 * INVN, rs0 = rsqrtf(qq0 * INVN - mu0 * mu0 + 1e-5f);
        float mu1 = s1 * INVN, rs1 = rsqrtf(qq1 * INVN - mu1 * mu1 + 1e-5f);
        unsigned long long* zt = zd + tile * 1280;
#pragma unroll
        for (int row = 0; row < 40; ++row) {
            float v0 = 0.f, v1 = 0.f;
            if (row >= 4 && row < 36) {
                float h0 = g_buf1[base + (row - 4) * 32 + r];
                float h1 = g_buf1[base + (row - 4) * 32 + r + 16];
                v0 = fmaxf(0.f, (h0 - mu0) * rs0);
                v1 = fmaxf(0.f, (h1 - mu1) * rs1);
            }
            zt[row * 32 + r]      = pack2(v0, v0);
            zt[row * 32 + r + 16] = pack2(v1, v1);
        }
    }
    __syncthreads();

    int o0 = (r & 3) * 8;                 // 4 o-groups of 8
    int tb = (r >> 2) * 8;                // 4 t-groups of 8
    ulonglong2 cba = *(const ulonglong2*)&cb[o0];
    ulonglong2 cbb = *(const ulonglong2*)&cb[o0 + 4];
    unsigned long long acc[8][4];
#pragma unroll
    for (int t = 0; t < 8; ++t) {
        acc[t][0] = cba.x; acc[t][1] = cba.y;
        acc[t][2] = cbb.x; acc[t][3] = cbb.y;
    }

    const unsigned long long* zt = zd + tile * 1280;
#pragma unroll 1
    for (int i = 0; i < 32; ++i) {
        unsigned long long z[16];
#pragma unroll
        for (int j = 0; j < 16; ++j) z[j] = zt[(tb + j) * 32 + i];
        const float* wk = ws + i * 32 + o0;
#pragma unroll
        for (int k = 0; k < KK; ++k) {
            ulonglong2 wa = *(const ulonglong2*)(wk + k * 1024);
            ulonglong2 wb = *(const ulonglong2*)(wk + k * 1024 + 4);
#pragma unroll
            for (int t = 0; t < 8; ++t) {
                unsigned long long zz = z[t + k];
                acc[t][0] = fma2(zz, wa.x, acc[t][0]);
                acc[t][1] = fma2(zz, wa.y, acc[t][1]);
                acc[t][2] = fma2(zz, wb.x, acc[t][2]);
                acc[t][3] = fma2(zz, wb.y, acc[t][3]);
            }
        }
    }

    // unpack, store (in-place), accumulate per-o stats (8 o's per thread)
    float av[8];
    float4 pa = make_float4(0.f,0.f,0.f,0.f), pb = pa, qa = pa, qb = pa;
#pragma unroll
    for (int t = 0; t < 8; ++t) {
        unpack2(acc[t][0], av[0], av[1]);
        unpack2(acc[t][1], av[2], av[3]);
        unpack2(acc[t][2], av[4], av[5]);
        unpack2(acc[t][3], av[6], av[7]);
        pa.x += av[0]; pa.y += av[1]; pa.z += av[2]; pa.w += av[3];
        pb.x += av[4]; pb.y += av[5]; pb.z += av[6]; pb.w += av[7];
        qa.x += av[0]*av[0]; qa.y += av[1]*av[1]; qa.z += av[2]*av[2]; qa.w += av[3]*av[3];
        qb.x += av[4]*av[4]; qb.y += av[5]*av[5]; qb.z += av[6]*av[6]; qb.w += av[7]*av[7];
        *(float4*)&g_buf1[base + (size_t)(tb + t) * 32 + o0]     = make_float4(av[0], av[1], av[2], av[3]);
        *(float4*)&g_buf1[base + (size_t)(tb + t) * 32 + o0 + 4] = make_float4(av[4], av[5], av[6], av[7]);
    }

    // stats2: lanes sharing lane&3 (masks 4,8,16 -> 8 lanes: 4 t-groups x 2 tiles,
    // all same b) share the same o-group.
#pragma unroll
    for (int m = 4; m <= 16; m <<= 1) {
        pa.x += __shfl_xor_sync(0xffffffff, pa.x, m);
        pa.y += __shfl_xor_sync(0xffffffff, pa.y, m);
        pa.z += __shfl_xor_sync(0xffffffff, pa.z, m);
        pa.w += __shfl_xor_sync(0xffffffff, pa.w, m);
        pb.x += __shfl_xor_sync(0xffffffff, pb.x, m);
        pb.y += __shfl_xor_sync(0xffffffff, pb.y, m);
        pb.z += __shfl_xor_sync(0xffffffff, pb.z, m);
        pb.w += __shfl_xor_sync(0xffffffff, pb.w, m);
        qa.x += __shfl_xor_sync(0xffffffff, qa.x, m);
        qa.y += __shfl_xor_sync(0xffffffff, qa.y, m);
        qa.z += __shfl_xor_sync(0xffffffff, qa.z, m);
        qa.w += __shfl_xor_sync(0xffffffff, qa.w, m);
        qb.x += __shfl_xor_sync(0xffffffff, qb.x, m);
        qb.y += __shfl_xor_sync(0xffffffff, qb.y, m);
        qb.z += __shfl_xor_sync(0xffffffff, qb.z, m);
        qb.w += __shfl_xor_sync(0xffffffff, qb.w, m);
    }
    __syncthreads();                       // all reads of zt done; reuse zd
    float4* sS = (float4*)zd;              // 4 arrays of 32 float4
    int warp = tid >> 5, lane = tid & 31;
    if (lane < 4) {
        int idx = warp * 4 + lane;
        sS[idx] = pa; sS[32 + idx] = pb; sS[64 + idx] = qa; sS[96 + idx] = qb;
    }
    __syncthreads();
    if (tid < 4) {
        float4 tpa = sS[tid], tpb = sS[32 + tid], tqa = sS[64 + tid], tqb = sS[96 + tid];
#pragma unroll
        for (int w = 1; w < 8; ++w) {
            float4 a = sS[w * 4 + tid], bq = sS[32 + w * 4 + tid];
            float4 cq = sS[64 + w * 4 + tid], dq = sS[96 + w * 4 + tid];
            tpa.x += a.x; tpa.y += a.y; tpa.z += a.z; tpa.w += a.w;
            tpb.x += bq.x; tpb.y += bq.y; tpb.z += bq.z; tpb.w += bq.w;
            tqa.x += cq.x; tqa.y += cq.y; tqa.z += cq.z; tqa.w += cq.w;
            tqb.x += dq.x; tqb.y += dq.y; tqb.z += dq.z; tqb.w += dq.w;
        }
        int basep = b * 32 + tid * 8;
        atomicAdd(&g_s2[basep + 0], tpa.x); atomicAdd(&g_s2[basep + 1], tpa.y);
        atomicAdd(&g_s2[basep + 2], tpa.z); atomicAdd(&g_s2[basep + 3], tpa.w);
        atomicAdd(&g_s2[basep + 4], tpb.x); atomicAdd(&g_s2[basep + 5], tpb.y);
        atomicAdd(&g_s2[basep + 6], tpb.z); atomicAdd(&g_s2[basep + 7], tpb.w);
        atomicAdd(&g_q2[basep + 0], tqa.x); atomicAdd(&g_q2[basep + 1], tqa.y);
        atomicAdd(&g_q2[basep + 2], tqa.z); atomicAdd(&g_q2[basep + 3], tqa.w);
        atomicAdd(&g_q2[basep + 4], tqb.x); atomicAdd(&g_q2[basep + 5], tqb.y);
        atomicAdd(&g_q2[basep + 6], tqb.z); atomicAdd(&g_q2[basep + 7], tqb.w);
    }
}

// ---------------- 5: IN2 + ReLU + residual + ReLU + transpose ----------------
__global__ void k_final(const float* __restrict__ x, float* __restrict__ out) {
    __shared__ float sy[32 * 33];
    int tid = threadIdx.x;
    int bc = blockIdx.x;
    int b = bc >> 12, c = bc & (CC - 1);
    size_t base = ((size_t)b * CC + c) * NSEG;
    int t = tid >> 3, o0 = (tid & 7) * 4;
    float4 v = *(const float4*)&g_buf1[base + (size_t)tid * 4];
    float4 s4 = *(const float4*)&g_s2[b * 32 + o0];
    float4 q4 = *(const float4*)&g_q2[b * 32 + o0];
    float4 mu, rs;
    mu.x = s4.x * INVN; rs.x = rsqrtf(q4.x * INVN - mu.x * mu.x + 1e-5f);
    mu.y = s4.y * INVN; rs.y = rsqrtf(q4.y * INVN - mu.y * mu.y + 1e-5f);
    mu.z = s4.z * INVN; rs.z = rsqrtf(q4.z * INVN - mu.z * mu.z + 1e-5f);
    mu.w = s4.w * INVN; rs.w = rsqrtf(q4.w * INVN - mu.w * mu.w + 1e-5f);
    sy[t * 33 + o0 + 0] = fmaxf(0.f, (v.x - mu.x) * rs.x);
    sy[t * 33 + o0 + 1] = fmaxf(0.f, (v.y - mu.y) * rs.y);
    sy[t * 33 + o0 + 2] = fmaxf(0.f, (v.z - mu.z) * rs.z);
    sy[t * 33 + o0 + 3] = fmaxf(0.f, (v.w - mu.w) * rs.w);
    __syncthreads();
    int f = tid >> 3, t0 = (tid & 7) * 4;
    size_t xi = (((size_t)b * FF + f) * CC + c) * TT + t0;
    float4 xv = *(const float4*)&x[xi];
    float4 o;
    o.x = fmaxf(0.f, sy[(t0 + 0) * 33 + f] + xv.x);
    o.y = fmaxf(0.f, sy[(t0 + 1) * 33 + f] + xv.y);
    o.z = fmaxf(0.f, sy[(t0 + 2) * 33 + f] + xv.z);
    o.w = fmaxf(0.f, sy[(t0 + 3) * 33 + f] + xv.w);
    *(float4*)&out[xi] = o;
}

// ---------------- launch ----------------
extern "C" void kernel_launch(void* const* d_in, const int* in_sizes, int n_in,
                              void* d_out, int out_size) {
    const float* x    = (const float*)d_in[0];
    const int*   ei   = (const int*)d_in[1];
    const float* ew   = (const float*)d_in[2];
    const float* W    = (const float*)d_in[3];
    const float* gcnb = (const float*)d_in[4];
    const float* cw   = (const float*)d_in[5];
    const float* cb   = (const float*)d_in[6];
    float* out = (float*)d_out;

    const int conv_smem = KK * 1024 * 4 + 16 * 1280 * 8;   // 36864 + 163840 = 200704
    cudaFuncSetAttribute(k_conv, cudaFuncAttributeMaxDynamicSharedMemorySize, conv_smem);

    // 5 launches; k_conv stays 4th => profiled next round.
    k_xlin <<<BB * CC, 256>>>(x, W);
    k_setup<<<1, 1024>>>(ei, ew);
    k_agg  <<<CC, 256>>>(gcnb);
    k_conv <<<BB * CC / 16, 256, conv_smem>>>(cw, cb);
    k_final<<<BB * CC, 256>>>(x, out);
}

// round 13
// speedup vs baseline: 1.6654x; 1.0898x over previous
#include <cuda_runtime.h>

#define BB 4
#define FF 32
#define CC 4096
#define TT 32
#define EE 65536
#define KK 9
#define NSEG 1024               // T*F floats per (b,c) tile
#define NTOT (BB*FF*CC*TT)      // 16777216
#define INVN (1.0f / 131072.0f) // 1/(CC*TT)

// ---------------- scratch (device globals; no allocs allowed) ----------------
__device__ float g_dis[CC];
__device__ int   g_off[CC + 1];
__device__ int   g_srcS[EE];     // CSR-sorted source node per slot
__device__ float g_nrmS[EE];     // CSR-sorted edge norm per slot
__device__ float g_buf0[NTOT];   // x_lin
__device__ float g_buf1[NTOT];   // h1 -> overwritten in-place by conv out
__device__ float g_s1[BB*FF], g_q1[BB*FF], g_s2[BB*FF], g_q2[BB*FF];

// ---------------- packed f32x2 helpers ----------------
__device__ __forceinline__ unsigned long long pack2(float x, float y) {
    unsigned long long r;
    asm("mov.b64 %0, {%1,%2};" : "=l"(r) : "f"(x), "f"(y));
    return r;
}
__device__ __forceinline__ void unpack2(unsigned long long v, float& x, float& y) {
    asm("mov.b64 {%0,%1}, %2;" : "=f"(x), "=f"(y) : "l"(v));
}
__device__ __forceinline__ unsigned long long fma2(unsigned long long a,
                                                   unsigned long long b,
                                                   unsigned long long c) {
    unsigned long long d;
    asm("fma.rn.f32x2 %0, %1, %2, %3;" : "=l"(d) : "l"(a), "l"(b), "l"(c));
    return d;
}

// ---------------- 1: x_lin[b,c,t,g] = sum_f x[b,f,c,t] * W[f,g] --------------
__global__ void k_xlin(const float* __restrict__ x, const float* __restrict__ W) {
    __shared__ float xs[32 * 33];
    __shared__ float ws[1024];          // [f][g]
    int tid = threadIdx.x;
    int bc = blockIdx.x;
    int b = bc >> 12, c = bc & (CC - 1);
    ((float4*)ws)[tid] = ((const float4*)W)[tid];
    int lf = tid >> 3, lt0 = (tid & 7) * 4;
    float4 xv = *(const float4*)&x[(((size_t)b * FF + lf) * CC + c) * TT + lt0];
    xs[(lt0 + 0) * 33 + lf] = xv.x;
    xs[(lt0 + 1) * 33 + lf] = xv.y;
    xs[(lt0 + 2) * 33 + lf] = xv.z;
    xs[(lt0 + 3) * 33 + lf] = xv.w;
    __syncthreads();
    int t = tid >> 3, g0 = (tid & 7) * 4;
    unsigned long long a0 = pack2(0.f, 0.f), a1 = pack2(0.f, 0.f);
#pragma unroll
    for (int f = 0; f < 32; ++f) {
        float z = xs[t * 33 + f];
        unsigned long long zz = pack2(z, z);
        ulonglong2 w2 = *(const ulonglong2*)&ws[f * 32 + g0];
        a0 = fma2(zz, w2.x, a0);
        a1 = fma2(zz, w2.y, a1);
    }
    float4 o;
    unpack2(a0, o.x, o.y);
    unpack2(a1, o.z, o.w);
    *(float4*)&g_buf0[((size_t)b * CC + c) * NSEG + (size_t)tid * 4] = o;
}

// ---------------- 2: fused prep + degree + scan + CSR fill -------------------
__global__ void k_setup(const int* __restrict__ ei, const float* __restrict__ ew) {
    __shared__ float s_deg[CC];
    __shared__ int   s_cnt[CC];
    __shared__ int   s_scan[1024];
    int tid = threadIdx.x;
#pragma unroll
    for (int i = tid; i < CC; i += 1024) { s_deg[i] = 1.0f; s_cnt[i] = 0; }
    if (tid < BB * FF) {
        g_s1[tid] = 0.f; g_q1[tid] = 0.f; g_s2[tid] = 0.f; g_q2[tid] = 0.f;
    }
    __syncthreads();
#pragma unroll 4
    for (int e = tid; e < EE; e += 1024) {
        int d = ei[EE + e];
        atomicAdd(&s_deg[d], ew[e]);
        atomicAdd(&s_cnt[d], 1);
    }
    __syncthreads();
    int c0 = tid * 4;
    int l0 = s_cnt[c0], l1 = s_cnt[c0+1], l2 = s_cnt[c0+2], l3 = s_cnt[c0+3];
    int tot = l0 + l1 + l2 + l3;
    s_scan[tid] = tot;
    __syncthreads();
    for (int d = 1; d < 1024; d <<= 1) {
        int v = 0;
        if (tid >= d) v = s_scan[tid - d];
        __syncthreads();
        if (tid >= d) s_scan[tid] += v;
        __syncthreads();
    }
    int excl = s_scan[tid] - tot;
    g_off[c0]   = excl;
    g_off[c0+1] = excl + l0;
    g_off[c0+2] = excl + l0 + l1;
    g_off[c0+3] = excl + l0 + l1 + l2;
    if (tid == 1023) g_off[CC] = s_scan[1023];
    s_cnt[c0]   = excl;
    s_cnt[c0+1] = excl + l0;
    s_cnt[c0+2] = excl + l0 + l1;
    s_cnt[c0+3] = excl + l0 + l1 + l2;
    float d0 = rsqrtf(s_deg[c0]),   d1 = rsqrtf(s_deg[c0+1]);
    float d2 = rsqrtf(s_deg[c0+2]), d3 = rsqrtf(s_deg[c0+3]);
    s_deg[c0] = d0; s_deg[c0+1] = d1; s_deg[c0+2] = d2; s_deg[c0+3] = d3;
    g_dis[c0] = d0; g_dis[c0+1] = d1; g_dis[c0+2] = d2; g_dis[c0+3] = d3;
    __syncthreads();
#pragma unroll 4
    for (int e = tid; e < EE; e += 1024) {
        int sN = ei[e];
        int d  = ei[EE + e];
        float w = ew[e];
        int slot = atomicAdd(&s_cnt[d], 1);
        g_srcS[slot] = sN;
        g_nrmS[slot] = s_deg[sN] * w * s_deg[d];
    }
}

// ---------------- 3: aggregate (gather, ALL 4 batches per block) + stats1 ----
__global__ void k_agg(const float* __restrict__ gcnb) {
    __shared__ int    s_src[64];
    __shared__ float  s_nrm[64];
    __shared__ float4 sP[64];
    __shared__ float4 sQ[64];
    int tid = threadIdx.x;
    int c = blockIdx.x;
    int off = tid * 4;
    float ds = g_dis[c];
    float d2 = ds * ds;
    float4 acc[BB];
#pragma unroll
    for (int b = 0; b < BB; ++b) {
        float4 v = *(const float4*)&g_buf0[((size_t)b * CC + c) * NSEG + off];
        acc[b] = make_float4(v.x * d2, v.y * d2, v.z * d2, v.w * d2);
    }
    int beg = g_off[c], end = g_off[c + 1];
    for (int j0 = beg; j0 < end; j0 += 64) {
        int n = min(64, end - j0);
        __syncthreads();
        if (tid < n) {
            s_src[tid] = g_srcS[j0 + tid];
            s_nrm[tid] = g_nrmS[j0 + tid];
        }
        __syncthreads();
        int j = 0;
        for (; j + 2 <= n; j += 2) {
            int s0 = s_src[j], s1 = s_src[j + 1];
            float n0 = s_nrm[j], n1 = s_nrm[j + 1];
            float4 v[2 * BB];
#pragma unroll
            for (int b = 0; b < BB; ++b) {
                v[b]      = *(const float4*)&g_buf0[((size_t)b * CC + s0) * NSEG + off];
                v[BB + b] = *(const float4*)&g_buf0[((size_t)b * CC + s1) * NSEG + off];
            }
#pragma unroll
            for (int b = 0; b < BB; ++b) {
                acc[b].x += v[b].x * n0; acc[b].y += v[b].y * n0;
                acc[b].z += v[b].z * n0; acc[b].w += v[b].w * n0;
                acc[b].x += v[BB+b].x * n1; acc[b].y += v[BB+b].y * n1;
                acc[b].z += v[BB+b].z * n1; acc[b].w += v[BB+b].w * n1;
            }
        }
        if (j < n) {
            int s0 = s_src[j];
            float n0 = s_nrm[j];
#pragma unroll
            for (int b = 0; b < BB; ++b) {
                float4 v = *(const float4*)&g_buf0[((size_t)b * CC + s0) * NSEG + off];
                acc[b].x += v.x * n0; acc[b].y += v.y * n0;
                acc[b].z += v.z * n0; acc[b].w += v.w * n0;
            }
        }
    }
    int g0 = off & 31;
    float4 bias = *(const float4*)&gcnb[g0];
    int warp = tid >> 5, lane = tid & 31;
#pragma unroll
    for (int b = 0; b < BB; ++b) {
        acc[b].x += bias.x; acc[b].y += bias.y;
        acc[b].z += bias.z; acc[b].w += bias.w;
        *(float4*)&g_buf1[((size_t)b * CC + c) * NSEG + off] = acc[b];
        float4 p = acc[b];
        float4 q = make_float4(p.x*p.x, p.y*p.y, p.z*p.z, p.w*p.w);
#pragma unroll
        for (int m = 8; m <= 16; m <<= 1) {
            p.x += __shfl_xor_sync(0xffffffff, p.x, m);
            p.y += __shfl_xor_sync(0xffffffff, p.y, m);
            p.z += __shfl_xor_sync(0xffffffff, p.z, m);
            p.w += __shfl_xor_sync(0xffffffff, p.w, m);
            q.x += __shfl_xor_sync(0xffffffff, q.x, m);
            q.y += __shfl_xor_sync(0xffffffff, q.y, m);
            q.z += __shfl_xor_sync(0xffffffff, q.z, m);
            q.w += __shfl_xor_sync(0xffffffff, q.w, m);
        }
        if (lane < 8) { sP[warp * 8 + lane] = p; sQ[warp * 8 + lane] = q; }
        __syncthreads();
        if (tid < 8) {
            float4 tp = sP[tid], tq = sQ[tid];
#pragma unroll
            for (int w = 1; w < 8; ++w) {
                float4 ap = sP[w * 8 + tid], aq = sQ[w * 8 + tid];
                tp.x += ap.x; tp.y += ap.y; tp.z += ap.z; tp.w += ap.w;
                tq.x += aq.x; tq.y += aq.y; tq.z += aq.z; tq.w += aq.w;
            }
            int base = b * 32 + tid * 4;
            atomicAdd(&g_s1[base + 0], tp.x); atomicAdd(&g_s1[base + 1], tp.y);
            atomicAdd(&g_s1[base + 2], tp.z); atomicAdd(&g_s1[base + 3], tp.w);
            atomicAdd(&g_q1[base + 0], tq.x); atomicAdd(&g_q1[base + 1], tq.y);
            atomicAdd(&g_q1[base + 2], tq.z); atomicAdd(&g_q1[base + 3], tq.w);
        }
        __syncthreads();
    }
}

// ---------------- 4: fused IN1+ReLU + temporal conv + bias + stats2 ----------
// Batch-pair version: block = 8 c-tiles (1 warp each) x 2 batches.
// z stored as {z_b0, z_b1} ull pairs in [i][row] layout -> fma2 multiplicand
// needs no splat; weights stored duplicated {w,w}. Warp-contiguous smem access.
// Thread = 8t x 4o x 2b. grid = (CC/8)*2.
__global__ void __launch_bounds__(256, 1)
k_conv(const float* __restrict__ cw, const float* __restrict__ cb) {
    extern __shared__ char dsm[];
    unsigned long long* wsd = (unsigned long long*)dsm;        // [k][i][o] dup, 73728B
    float* muS = (float*)(dsm + 73728);                         // [2][32]
    float* rsS = muS + 64;                                      // [2][32]
    unsigned long long* zd = (unsigned long long*)(dsm + 73728 + 512); // 8x1280
    int tid = threadIdx.x;
    int warp = tid >> 5, lane = tid & 31;
    int blk = blockIdx.x;
    int bp = blk & 1;
    int c8 = blk >> 1;
    int b0 = bp * 2, b1 = bp * 2 + 1;
    int c = c8 * 8 + warp;

    // duplicated weights {w,w}
    for (int idx = tid; idx < 9216; idx += 256) {
        int k = idx >> 10;
        int rem = idx & 1023;
        int i = rem >> 5, o = rem & 31;
        float w = cw[(o * 32 + i) * KK + k];
        wsd[idx] = pack2(w, w);
    }
    // mu/rs for both batches of the pair
    if (tid < 64) {
        int bb = tid >> 5;
        int i = tid & 31;
        int gb = bp * 2 + bb;
        float s = g_s1[gb * 32 + i], qq = g_q1[gb * 32 + i];
        float mu = s * INVN;
        float rs = rsqrtf(qq * INVN - mu * mu + 1e-5f);
        muS[bb * 32 + i] = mu;
        rsS[bb * 32 + i] = rs;
    }
    __syncthreads();

    size_t base0 = ((size_t)b0 * CC + c) * NSEG;
    size_t base1 = ((size_t)b1 * CC + c) * NSEG;
    unsigned long long* zt = zd + warp * 1280;   // [i][row]: i*40 + row

    // fill z pairs, IN1+ReLU fused; float4-coalesced gmem reads
    {
        int i0 = (lane & 7) * 4;
        int rsub = lane >> 3;                    // 0..3
        float4 mu0 = *(const float4*)&muS[i0];
        float4 rs0 = *(const float4*)&rsS[i0];
        float4 mu1 = *(const float4*)&muS[32 + i0];
        float4 rs1 = *(const float4*)&rsS[32 + i0];
#pragma unroll
        for (int pass = 0; pass < 10; ++pass) {
            int row = pass * 4 + rsub;
            float4 v0 = make_float4(0.f, 0.f, 0.f, 0.f);
            float4 v1 = v0;
            if (row >= 4 && row < 36) {
                float4 h0 = *(const float4*)&g_buf1[base0 + (size_t)(row - 4) * 32 + i0];
                float4 h1 = *(const float4*)&g_buf1[base1 + (size_t)(row - 4) * 32 + i0];
                v0.x = fmaxf(0.f, (h0.x - mu0.x) * rs0.x);
                v0.y = fmaxf(0.f, (h0.y - mu0.y) * rs0.y);
                v0.z = fmaxf(0.f, (h0.z - mu0.z) * rs0.z);
                v0.w = fmaxf(0.f, (h0.w - mu0.w) * rs0.w);
                v1.x = fmaxf(0.f, (h1.x - mu1.x) * rs1.x);
                v1.y = fmaxf(0.f, (h1.y - mu1.y) * rs1.y);
                v1.z = fmaxf(0.f, (h1.z - mu1.z) * rs1.z);
                v1.w = fmaxf(0.f, (h1.w - mu1.w) * rs1.w);
            }
            zt[(i0 + 0) * 40 + row] = pack2(v0.x, v1.x);
            zt[(i0 + 1) * 40 + row] = pack2(v0.y, v1.y);
            zt[(i0 + 2) * 40 + row] = pack2(v0.z, v1.z);
            zt[(i0 + 3) * 40 + row] = pack2(v0.w, v1.w);
        }
    }
    __syncthreads();

    int o0 = (lane & 7) * 4;
    int tb = (lane >> 3) * 8;
    float4 cbv = *(const float4*)&cb[o0];
    unsigned long long acc[8][4];                // [t][o-in-group], pair over b
#pragma unroll
    for (int t = 0; t < 8; ++t) {
        acc[t][0] = pack2(cbv.x, cbv.x);
        acc[t][1] = pack2(cbv.y, cbv.y);
        acc[t][2] = pack2(cbv.z, cbv.z);
        acc[t][3] = pack2(cbv.w, cbv.w);
    }

#pragma unroll 1
    for (int i = 0; i < 32; ++i) {
        unsigned long long z[16];
        const ulonglong2* zp = (const ulonglong2*)&zt[i * 40 + tb];
#pragma unroll
        for (int j = 0; j < 8; ++j) {
            ulonglong2 t2 = zp[j];
            z[2 * j] = t2.x;
            z[2 * j + 1] = t2.y;
        }
        const unsigned long long* wk = wsd + i * 32 + o0;
#pragma unroll
        for (int k = 0; k < KK; ++k) {
            ulonglong2 wA = *(const ulonglong2*)(wk + k * 1024);
            ulonglong2 wB = *(const ulonglong2*)(wk + k * 1024 + 2);
#pragma unroll
            for (int t = 0; t < 8; ++t) {
                unsigned long long zz = z[t + k];
                acc[t][0] = fma2(zz, wA.x, acc[t][0]);
                acc[t][1] = fma2(zz, wA.y, acc[t][1]);
                acc[t][2] = fma2(zz, wB.x, acc[t][2]);
                acc[t][3] = fma2(zz, wB.y, acc[t][3]);
            }
        }
    }

    // unpack, store both batches in-place, accumulate stats per (b, o)
    float4 p0 = make_float4(0.f, 0.f, 0.f, 0.f), p1 = p0, q0 = p0, q1 = p0;
#pragma unroll
    for (int t = 0; t < 8; ++t) {
        float a0[4], a1[4];
        unpack2(acc[t][0], a0[0], a1[0]);
        unpack2(acc[t][1], a0[1], a1[1]);
        unpack2(acc[t][2], a0[2], a1[2]);
        unpack2(acc[t][3], a0[3], a1[3]);
        p0.x += a0[0]; p0.y += a0[1]; p0.z += a0[2]; p0.w += a0[3];
        p1.x += a1[0]; p1.y += a1[1]; p1.z += a1[2]; p1.w += a1[3];
        q0.x += a0[0]*a0[0]; q0.y += a0[1]*a0[1]; q0.z += a0[2]*a0[2]; q0.w += a0[3]*a0[3];
        q1.x += a1[0]*a1[0]; q1.y += a1[1]*a1[1]; q1.z += a1[2]*a1[2]; q1.w += a1[3]*a1[3];
        *(float4*)&g_buf1[base0 + (size_t)(tb + t) * 32 + o0] = make_float4(a0[0], a0[1], a0[2], a0[3]);
        *(float4*)&g_buf1[base1 + (size_t)(tb + t) * 32 + o0] = make_float4(a1[0], a1[1], a1[2], a1[3]);
    }

    // reduce over t-groups (lanes sharing lane&7): masks 8, 16
#pragma unroll
    for (int m = 8; m <= 16; m <<= 1) {
        p0.x += __shfl_xor_sync(0xffffffff, p0.x, m);
        p0.y += __shfl_xor_sync(0xffffffff, p0.y, m);
        p0.z += __shfl_xor_sync(0xffffffff, p0.z, m);
        p0.w += __shfl_xor_sync(0xffffffff, p0.w, m);
        p1.x += __shfl_xor_sync(0xffffffff, p1.x, m);
        p1.y += __shfl_xor_sync(0xffffffff, p1.y, m);
        p1.z += __shfl_xor_sync(0xffffffff, p1.z, m);
        p1.w += __shfl_xor_sync(0xffffffff, p1.w, m);
        q0.x += __shfl_xor_sync(0xffffffff, q0.x, m);
        q0.y += __shfl_xor_sync(0xffffffff, q0.y, m);
        q0.z += __shfl_xor_sync(0xffffffff, q0.z, m);
        q0.w += __shfl_xor_sync(0xffffffff, q0.w, m);
        q1.x += __shfl_xor_sync(0xffffffff, q1.x, m);
        q1.y += __shfl_xor_sync(0xffffffff, q1.y, m);
        q1.z += __shfl_xor_sync(0xffffffff, q1.z, m);
        q1.w += __shfl_xor_sync(0xffffffff, q1.w, m);
    }
    __syncthreads();                    // all reads of zt done; reuse zd
    float4* sP0 = (float4*)zd;          // 64 each
    float4* sP1 = sP0 + 64;
    float4* sQ0 = sP1 + 64;
    float4* sQ1 = sQ0 + 64;
    if (lane < 8) {
        int idx = warp * 8 + lane;
        sP0[idx] = p0; sP1[idx] = p1; sQ0[idx] = q0; sQ1[idx] = q1;
    }
    __syncthreads();
    if (tid < 8) {
        float4 tp0 = sP0[tid], tp1 = sP1[tid], tq0 = sQ0[tid], tq1 = sQ1[tid];
#pragma unroll
        for (int w = 1; w < 8; ++w) {
            float4 a = sP0[w * 8 + tid], bq = sP1[w * 8 + tid];
            float4 cq = sQ0[w * 8 + tid], dq = sQ1[w * 8 + tid];
            tp0.x += a.x; tp0.y += a.y; tp0.z += a.z; tp0.w += a.w;
            tp1.x += bq.x; tp1.y += bq.y; tp1.z += bq.z; tp1.w += bq.w;
            tq0.x += cq.x; tq0.y += cq.y; tq0.z += cq.z; tq0.w += cq.w;
            tq1.x += dq.x; tq1.y += dq.y; tq1.z += dq.z; tq1.w += dq.w;
        }
        int ba0 = b0 * 32 + tid * 4;
        int ba1 = b1 * 32 + tid * 4;
        atomicAdd(&g_s2[ba0 + 0], tp0.x); atomicAdd(&g_s2[ba0 + 1], tp0.y);
        atomicAdd(&g_s2[ba0 + 2], tp0.z); atomicAdd(&g_s2[ba0 + 3], tp0.w);
        atomicAdd(&g_s2[ba1 + 0], tp1.x); atomicAdd(&g_s2[ba1 + 1], tp1.y);
        atomicAdd(&g_s2[ba1 + 2], tp1.z); atomicAdd(&g_s2[ba1 + 3], tp1.w);
        atomicAdd(&g_q2[ba0 + 0], tq0.x); atomicAdd(&g_q2[ba0 + 1], tq0.y);
        atomicAdd(&g_q2[ba0 + 2], tq0.z); atomicAdd(&g_q2[ba0 + 3], tq0.w);
        atomicAdd(&g_q2[ba1 + 0], tq1.x); atomicAdd(&g_q2[ba1 + 1], tq1.y);
        atomicAdd(&g_q2[ba1 + 2], tq1.z); atomicAdd(&g_q2[ba1 + 3], tq1.w);
    }
}

// ---------------- 5: IN2 + ReLU + residual + ReLU + transpose ----------------
__global__ void k_final(const float* __restrict__ x, float* __restrict__ out) {
    __shared__ float sy[32 * 33];
    int tid = threadIdx.x;
    int bc = blockIdx.x;
    int b = bc >> 12, c = bc & (CC - 1);
    size_t base = ((size_t)b * CC + c) * NSEG;
    int t = tid >> 3, o0 = (tid & 7) * 4;
    float4 v = *(const float4*)&g_buf1[base + (size_t)tid * 4];
    float4 s4 = *(const float4*)&g_s2[b * 32 + o0];
    float4 q4 = *(const float4*)&g_q2[b * 32 + o0];
    float4 mu, rs;
    mu.x = s4.x * INVN; rs.x = rsqrtf(q4.x * INVN - mu.x * mu.x + 1e-5f);
    mu.y = s4.y * INVN; rs.y = rsqrtf(q4.y * INVN - mu.y * mu.y + 1e-5f);
    mu.z = s4.z * INVN; rs.z = rsqrtf(q4.z * INVN - mu.z * mu.z + 1e-5f);
    mu.w = s4.w * INVN; rs.w = rsqrtf(q4.w * INVN - mu.w * mu.w + 1e-5f);
    sy[t * 33 + o0 + 0] = fmaxf(0.f, (v.x - mu.x) * rs.x);
    sy[t * 33 + o0 + 1] = fmaxf(0.f, (v.y - mu.y) * rs.y);
    sy[t * 33 + o0 + 2] = fmaxf(0.f, (v.z - mu.z) * rs.z);
    sy[t * 33 + o0 + 3] = fmaxf(0.f, (v.w - mu.w) * rs.w);
    __syncthreads();
    int f = tid >> 3, t0 = (tid & 7) * 4;
    size_t xi = (((size_t)b * FF + f) * CC + c) * TT + t0;
    float4 xv = *(const float4*)&x[xi];
    float4 o;
    o.x = fmaxf(0.f, sy[(t0 + 0) * 33 + f] + xv.x);
    o.y = fmaxf(0.f, sy[(t0 + 1) * 33 + f] + xv.y);
    o.z = fmaxf(0.f, sy[(t0 + 2) * 33 + f] + xv.z);
    o.w = fmaxf(0.f, sy[(t0 + 3) * 33 + f] + xv.w);
    *(float4*)&out[xi] = o;
}

// ---------------- launch ----------------
extern "C" void kernel_launch(void* const* d_in, const int* in_sizes, int n_in,
                              void* d_out, int out_size) {
    const float* x    = (const float*)d_in[0];
    const int*   ei   = (const int*)d_in[1];
    const float* ew   = (const float*)d_in[2];
    const float* W    = (const float*)d_in[3];
    const float* gcnb = (const float*)d_in[4];
    const float* cw   = (const float*)d_in[5];
    const float* cb   = (const float*)d_in[6];
    float* out = (float*)d_out;

    const int conv_smem = 73728 + 512 + 8 * 1280 * 8;   // 156160
    cudaFuncSetAttribute(k_conv, cudaFuncAttributeMaxDynamicSharedMemorySize, conv_smem);

    // 5 launches; k_conv stays 4th => profiled next round.
    k_xlin <<<BB * CC, 256>>>(x, W);
    k_setup<<<1, 1024>>>(ei, ew);
    k_agg  <<<CC, 256>>>(gcnb);
    k_conv <<<(CC / 8) * 2, 256, conv_smem>>>(cw, cb);
    k_final<<<BB * CC, 256>>>(x, out);
}

// round 14
// speedup vs baseline: 1.6975x; 1.0193x over previous
#include <cuda_runtime.h>

#define BB 4
#define FF 32
#define CC 4096
#define TT 32
#define EE 65536
#define KK 9
#define NSEG 1024               // T*F floats per (b,c) tile
#define NTOT (BB*FF*CC*TT)      // 16777216
#define INVN (1.0f / 131072.0f) // 1/(CC*TT)

// ---------------- scratch (device globals; no allocs allowed) ----------------
__device__ float g_dis[CC];
__device__ int   g_off[CC + 1];
__device__ int   g_srcS[EE];     // CSR-sorted source node per slot
__device__ float g_nrmS[EE];     // CSR-sorted edge norm per slot
__device__ float g_buf0[NTOT];   // x_lin
__device__ float g_buf1[NTOT];   // h1 -> overwritten in-place by conv out
__device__ float g_s1[BB*FF], g_q1[BB*FF], g_s2[BB*FF], g_q2[BB*FF];

// ---------------- packed f32x2 helpers ----------------
__device__ __forceinline__ unsigned long long pack2(float x, float y) {
    unsigned long long r;
    asm("mov.b64 %0, {%1,%2};" : "=l"(r) : "f"(x), "f"(y));
    return r;
}
__device__ __forceinline__ void unpack2(unsigned long long v, float& x, float& y) {
    asm("mov.b64 {%0,%1}, %2;" : "=f"(x), "=f"(y) : "l"(v));
}
__device__ __forceinline__ unsigned long long fma2(unsigned long long a,
                                                   unsigned long long b,
                                                   unsigned long long c) {
    unsigned long long d;
    asm("fma.rn.f32x2 %0, %1, %2, %3;" : "=l"(d) : "l"(a), "l"(b), "l"(c));
    return d;
}

// ---------------- 1: x_lin[b,c,t,g] = sum_f x[b,f,c,t] * W[f,g] --------------
__global__ void k_xlin(const float* __restrict__ x, const float* __restrict__ W) {
    __shared__ float xs[32 * 33];
    __shared__ float ws[1024];          // [f][g]
    int tid = threadIdx.x;
    int bc = blockIdx.x;
    int b = bc >> 12, c = bc & (CC - 1);
    ((float4*)ws)[tid] = ((const float4*)W)[tid];
    int lf = tid >> 3, lt0 = (tid & 7) * 4;
    float4 xv = *(const float4*)&x[(((size_t)b * FF + lf) * CC + c) * TT + lt0];
    xs[(lt0 + 0) * 33 + lf] = xv.x;
    xs[(lt0 + 1) * 33 + lf] = xv.y;
    xs[(lt0 + 2) * 33 + lf] = xv.z;
    xs[(lt0 + 3) * 33 + lf] = xv.w;
    __syncthreads();
    int t = tid >> 3, g0 = (tid & 7) * 4;
    unsigned long long a0 = pack2(0.f, 0.f), a1 = pack2(0.f, 0.f);
#pragma unroll
    for (int f = 0; f < 32; ++f) {
        float z = xs[t * 33 + f];
        unsigned long long zz = pack2(z, z);
        ulonglong2 w2 = *(const ulonglong2*)&ws[f * 32 + g0];
        a0 = fma2(zz, w2.x, a0);
        a1 = fma2(zz, w2.y, a1);
    }
    float4 o;
    unpack2(a0, o.x, o.y);
    unpack2(a1, o.z, o.w);
    *(float4*)&g_buf0[((size_t)b * CC + c) * NSEG + (size_t)tid * 4] = o;
}

// ---------------- 2: fused prep + degree + scan + CSR fill -------------------
__global__ void k_setup(const int* __restrict__ ei, const float* __restrict__ ew) {
    __shared__ float s_deg[CC];
    __shared__ int   s_cnt[CC];
    __shared__ int   s_scan[1024];
    int tid = threadIdx.x;
#pragma unroll
    for (int i = tid; i < CC; i += 1024) { s_deg[i] = 1.0f; s_cnt[i] = 0; }
    if (tid < BB * FF) {
        g_s1[tid] = 0.f; g_q1[tid] = 0.f; g_s2[tid] = 0.f; g_q2[tid] = 0.f;
    }
    __syncthreads();
#pragma unroll 4
    for (int e = tid; e < EE; e += 1024) {
        int d = ei[EE + e];
        atomicAdd(&s_deg[d], ew[e]);
        atomicAdd(&s_cnt[d], 1);
    }
    __syncthreads();
    int c0 = tid * 4;
    int l0 = s_cnt[c0], l1 = s_cnt[c0+1], l2 = s_cnt[c0+2], l3 = s_cnt[c0+3];
    int tot = l0 + l1 + l2 + l3;
    s_scan[tid] = tot;
    __syncthreads();
    for (int d = 1; d < 1024; d <<= 1) {
        int v = 0;
        if (tid >= d) v = s_scan[tid - d];
        __syncthreads();
        if (tid >= d) s_scan[tid] += v;
        __syncthreads();
    }
    int excl = s_scan[tid] - tot;
    g_off[c0]   = excl;
    g_off[c0+1] = excl + l0;
    g_off[c0+2] = excl + l0 + l1;
    g_off[c0+3] = excl + l0 + l1 + l2;
    if (tid == 1023) g_off[CC] = s_scan[1023];
    s_cnt[c0]   = excl;
    s_cnt[c0+1] = excl + l0;
    s_cnt[c0+2] = excl + l0 + l1;
    s_cnt[c0+3] = excl + l0 + l1 + l2;
    float d0 = rsqrtf(s_deg[c0]),   d1 = rsqrtf(s_deg[c0+1]);
    float d2 = rsqrtf(s_deg[c0+2]), d3 = rsqrtf(s_deg[c0+3]);
    s_deg[c0] = d0; s_deg[c0+1] = d1; s_deg[c0+2] = d2; s_deg[c0+3] = d3;
    g_dis[c0] = d0; g_dis[c0+1] = d1; g_dis[c0+2] = d2; g_dis[c0+3] = d3;
    __syncthreads();
#pragma unroll 4
    for (int e = tid; e < EE; e += 1024) {
        int sN = ei[e];
        int d  = ei[EE + e];
        float w = ew[e];
        int slot = atomicAdd(&s_cnt[d], 1);
        g_srcS[slot] = sN;
        g_nrmS[slot] = s_deg[sN] * w * s_deg[d];
    }
}

// ---------------- 3: aggregate (gather, ALL 4 batches per block) + stats1 ----
__global__ void k_agg(const float* __restrict__ gcnb) {
    __shared__ int    s_src[64];
    __shared__ float  s_nrm[64];
    __shared__ float4 sP[64];
    __shared__ float4 sQ[64];
    int tid = threadIdx.x;
    int c = blockIdx.x;
    int off = tid * 4;
    float ds = g_dis[c];
    float d2 = ds * ds;
    float4 acc[BB];
#pragma unroll
    for (int b = 0; b < BB; ++b) {
        float4 v = *(const float4*)&g_buf0[((size_t)b * CC + c) * NSEG + off];
        acc[b] = make_float4(v.x * d2, v.y * d2, v.z * d2, v.w * d2);
    }
    int beg = g_off[c], end = g_off[c + 1];
    for (int j0 = beg; j0 < end; j0 += 64) {
        int n = min(64, end - j0);
        __syncthreads();
        if (tid < n) {
            s_src[tid] = g_srcS[j0 + tid];
            s_nrm[tid] = g_nrmS[j0 + tid];
        }
        __syncthreads();
        int j = 0;
        for (; j + 2 <= n; j += 2) {
            int s0 = s_src[j], s1 = s_src[j + 1];
            float n0 = s_nrm[j], n1 = s_nrm[j + 1];
            float4 v[2 * BB];
#pragma unroll
            for (int b = 0; b < BB; ++b) {
                v[b]      = *(const float4*)&g_buf0[((size_t)b * CC + s0) * NSEG + off];
                v[BB + b] = *(const float4*)&g_buf0[((size_t)b * CC + s1) * NSEG + off];
            }
#pragma unroll
            for (int b = 0; b < BB; ++b) {
                acc[b].x += v[b].x * n0; acc[b].y += v[b].y * n0;
                acc[b].z += v[b].z * n0; acc[b].w += v[b].w * n0;
                acc[b].x += v[BB+b].x * n1; acc[b].y += v[BB+b].y * n1;
                acc[b].z += v[BB+b].z * n1; acc[b].w += v[BB+b].w * n1;
            }
        }
        if (j < n) {
            int s0 = s_src[j];
            float n0 = s_nrm[j];
#pragma unroll
            for (int b = 0; b < BB; ++b) {
                float4 v = *(const float4*)&g_buf0[((size_t)b * CC + s0) * NSEG + off];
                acc[b].x += v.x * n0; acc[b].y += v.y * n0;
                acc[b].z += v.z * n0; acc[b].w += v.w * n0;
            }
        }
    }
    int g0 = off & 31;
    float4 bias = *(const float4*)&gcnb[g0];
    int warp = tid >> 5, lane = tid & 31;
#pragma unroll
    for (int b = 0; b < BB; ++b) {
        acc[b].x += bias.x; acc[b].y += bias.y;
        acc[b].z += bias.z; acc[b].w += bias.w;
        *(float4*)&g_buf1[((size_t)b * CC + c) * NSEG + off] = acc[b];
        float4 p = acc[b];
        float4 q = make_float4(p.x*p.x, p.y*p.y, p.z*p.z, p.w*p.w);
#pragma unroll
        for (int m = 8; m <= 16; m <<= 1) {
            p.x += __shfl_xor_sync(0xffffffff, p.x, m);
            p.y += __shfl_xor_sync(0xffffffff, p.y, m);
            p.z += __shfl_xor_sync(0xffffffff, p.z, m);
            p.w += __shfl_xor_sync(0xffffffff, p.w, m);
            q.x += __shfl_xor_sync(0xffffffff, q.x, m);
            q.y += __shfl_xor_sync(0xffffffff, q.y, m);
            q.z += __shfl_xor_sync(0xffffffff, q.z, m);
            q.w += __shfl_xor_sync(0xffffffff, q.w, m);
        }
        if (lane < 8) { sP[warp * 8 + lane] = p; sQ[warp * 8 + lane] = q; }
        __syncthreads();
        if (tid < 8) {
            float4 tp = sP[tid], tq = sQ[tid];
#pragma unroll
            for (int w = 1; w < 8; ++w) {
                float4 ap = sP[w * 8 + tid], aq = sQ[w * 8 + tid];
                tp.x += ap.x; tp.y += ap.y; tp.z += ap.z; tp.w += ap.w;
                tq.x += aq.x; tq.y += aq.y; tq.z += aq.z; tq.w += aq.w;
            }
            int base = b * 32 + tid * 4;
            atomicAdd(&g_s1[base + 0], tp.x); atomicAdd(&g_s1[base + 1], tp.y);
            atomicAdd(&g_s1[base + 2], tp.z); atomicAdd(&g_s1[base + 3], tp.w);
            atomicAdd(&g_q1[base + 0], tq.x); atomicAdd(&g_q1[base + 1], tq.y);
            atomicAdd(&g_q1[base + 2], tq.z); atomicAdd(&g_q1[base + 3], tq.w);
        }
        __syncthreads();
    }
}

// ---------------- 4: fused IN1+ReLU + temporal conv + bias + stats2 ----------
// Batch-pair version: block = 8 c-tiles (1 warp each) x 2 batches.
// z stored as {z_b0, z_b1} ull pairs in [i][row] layout; weights duplicated
// {w,w}. Thread = 8t x 4o x 2b. grid = (CC/8)*2.
// i-loop unroll 2: lets ptxas pipeline iteration i+1's LDS under i's fma burst.
__global__ void __launch_bounds__(256, 1)
k_conv(const float* __restrict__ cw, const float* __restrict__ cb) {
    extern __shared__ char dsm[];
    unsigned long long* wsd = (unsigned long long*)dsm;        // [k][i][o] dup, 73728B
    float* muS = (float*)(dsm + 73728);                         // [2][32]
    float* rsS = muS + 64;                                      // [2][32]
    unsigned long long* zd = (unsigned long long*)(dsm + 73728 + 512); // 8x1280
    int tid = threadIdx.x;
    int warp = tid >> 5, lane = tid & 31;
    int blk = blockIdx.x;
    int bp = blk & 1;
    int c8 = blk >> 1;
    int b0 = bp * 2, b1 = bp * 2 + 1;
    int c = c8 * 8 + warp;

    // duplicated weights {w,w}
    for (int idx = tid; idx < 9216; idx += 256) {
        int k = idx >> 10;
        int rem = idx & 1023;
        int i = rem >> 5, o = rem & 31;
        float w = cw[(o * 32 + i) * KK + k];
        wsd[idx] = pack2(w, w);
    }
    // mu/rs for both batches of the pair
    if (tid < 64) {
        int bb = tid >> 5;
        int i = tid & 31;
        int gb = bp * 2 + bb;
        float s = g_s1[gb * 32 + i], qq = g_q1[gb * 32 + i];
        float mu = s * INVN;
        float rs = rsqrtf(qq * INVN - mu * mu + 1e-5f);
        muS[bb * 32 + i] = mu;
        rsS[bb * 32 + i] = rs;
    }
    __syncthreads();

    size_t base0 = ((size_t)b0 * CC + c) * NSEG;
    size_t base1 = ((size_t)b1 * CC + c) * NSEG;
    unsigned long long* zt = zd + warp * 1280;   // [i][row]: i*40 + row

    // fill z pairs, IN1+ReLU fused; float4-coalesced gmem reads
    {
        int i0 = (lane & 7) * 4;
        int rsub = lane >> 3;                    // 0..3
        float4 mu0 = *(const float4*)&muS[i0];
        float4 rs0 = *(const float4*)&rsS[i0];
        float4 mu1 = *(const float4*)&muS[32 + i0];
        float4 rs1 = *(const float4*)&rsS[32 + i0];
#pragma unroll
        for (int pass = 0; pass < 10; ++pass) {
            int row = pass * 4 + rsub;
            float4 v0 = make_float4(0.f, 0.f, 0.f, 0.f);
            float4 v1 = v0;
            if (row >= 4 && row < 36) {
                float4 h0 = *(const float4*)&g_buf1[base0 + (size_t)(row - 4) * 32 + i0];
                float4 h1 = *(const float4*)&g_buf1[base1 + (size_t)(row - 4) * 32 + i0];
                v0.x = fmaxf(0.f, (h0.x - mu0.x) * rs0.x);
                v0.y = fmaxf(0.f, (h0.y - mu0.y) * rs0.y);
                v0.z = fmaxf(0.f, (h0.z - mu0.z) * rs0.z);
                v0.w = fmaxf(0.f, (h0.w - mu0.w) * rs0.w);
                v1.x = fmaxf(0.f, (h1.x - mu1.x) * rs1.x);
                v1.y = fmaxf(0.f, (h1.y - mu1.y) * rs1.y);
                v1.z = fmaxf(0.f, (h1.z - mu1.z) * rs1.z);
                v1.w = fmaxf(0.f, (h1.w - mu1.w) * rs1.w);
            }
            zt[(i0 + 0) * 40 + row] = pack2(v0.x, v1.x);
            zt[(i0 + 1) * 40 + row] = pack2(v0.y, v1.y);
            zt[(i0 + 2) * 40 + row] = pack2(v0.z, v1.z);
            zt[(i0 + 3) * 40 + row] = pack2(v0.w, v1.w);
        }
    }
    __syncthreads();

    int o0 = (lane & 7) * 4;
    int tb = (lane >> 3) * 8;
    float4 cbv = *(const float4*)&cb[o0];
    unsigned long long acc[8][4];                // [t][o-in-group], pair over b
#pragma unroll
    for (int t = 0; t < 8; ++t) {
        acc[t][0] = pack2(cbv.x, cbv.x);
        acc[t][1] = pack2(cbv.y, cbv.y);
        acc[t][2] = pack2(cbv.z, cbv.z);
        acc[t][3] = pack2(cbv.w, cbv.w);
    }

#pragma unroll 2
    for (int i = 0; i < 32; ++i) {
        unsigned long long z[16];
        const ulonglong2* zp = (const ulonglong2*)&zt[i * 40 + tb];
#pragma unroll
        for (int j = 0; j < 8; ++j) {
            ulonglong2 t2 = zp[j];
            z[2 * j] = t2.x;
            z[2 * j + 1] = t2.y;
        }
        const unsigned long long* wk = wsd + i * 32 + o0;
#pragma unroll
        for (int k = 0; k < KK; ++k) {
            ulonglong2 wA = *(const ulonglong2*)(wk + k * 1024);
            ulonglong2 wB = *(const ulonglong2*)(wk + k * 1024 + 2);
#pragma unroll
            for (int t = 0; t < 8; ++t) {
                unsigned long long zz = z[t + k];
                acc[t][0] = fma2(zz, wA.x, acc[t][0]);
                acc[t][1] = fma2(zz, wA.y, acc[t][1]);
                acc[t][2] = fma2(zz, wB.x, acc[t][2]);
                acc[t][3] = fma2(zz, wB.y, acc[t][3]);
            }
        }
    }

    // unpack, store both batches in-place, accumulate stats per (b, o)
    float4 p0 = make_float4(0.f, 0.f, 0.f, 0.f), p1 = p0, q0 = p0, q1 = p0;
#pragma unroll
    for (int t = 0; t < 8; ++t) {
        float a0[4], a1[4];
        unpack2(acc[t][0], a0[0], a1[0]);
        unpack2(acc[t][1], a0[1], a1[1]);
        unpack2(acc[t][2], a0[2], a1[2]);
        unpack2(acc[t][3], a0[3], a1[3]);
        p0.x += a0[0]; p0.y += a0[1]; p0.z += a0[2]; p0.w += a0[3];
        p1.x += a1[0]; p1.y += a1[1]; p1.z += a1[2]; p1.w += a1[3];
        q0.x += a0[0]*a0[0]; q0.y += a0[1]*a0[1]; q0.z += a0[2]*a0[2]; q0.w += a0[3]*a0[3];
        q1.x += a1[0]*a1[0]; q1.y += a1[1]*a1[1]; q1.z += a1[2]*a1[2]; q1.w += a1[3]*a1[3];
        *(float4*)&g_buf1[base0 + (size_t)(tb + t) * 32 + o0] = make_float4(a0[0], a0[1], a0[2], a0[3]);
        *(float4*)&g_buf1[base1 + (size_t)(tb + t) * 32 + o0] = make_float4(a1[0], a1[1], a1[2], a1[3]);
    }

    // reduce over t-groups (lanes sharing lane&7): masks 8, 16
#pragma unroll
    for (int m = 8; m <= 16; m <<= 1) {
        p0.x += __shfl_xor_sync(0xffffffff, p0.x, m);
        p0.y += __shfl_xor_sync(0xffffffff, p0.y, m);
        p0.z += __shfl_xor_sync(0xffffffff, p0.z, m);
        p0.w += __shfl_xor_sync(0xffffffff, p0.w, m);
        p1.x += __shfl_xor_sync(0xffffffff, p1.x, m);
        p1.y += __shfl_xor_sync(0xffffffff, p1.y, m);
        p1.z += __shfl_xor_sync(0xffffffff, p1.z, m);
        p1.w += __shfl_xor_sync(0xffffffff, p1.w, m);
        q0.x += __shfl_xor_sync(0xffffffff, q0.x, m);
        q0.y += __shfl_xor_sync(0xffffffff, q0.y, m);
        q0.z += __shfl_xor_sync(0xffffffff, q0.z, m);
        q0.w += __shfl_xor_sync(0xffffffff, q0.w, m);
        q1.x += __shfl_xor_sync(0xffffffff, q1.x, m);
        q1.y += __shfl_xor_sync(0xffffffff, q1.y, m);
        q1.z += __shfl_xor_sync(0xffffffff, q1.z, m);
        q1.w += __shfl_xor_sync(0xffffffff, q1.w, m);
    }
    __syncthreads();                    // all reads of zt done; reuse zd
    float4* sP0 = (float4*)zd;          // 64 each
    float4* sP1 = sP0 + 64;
    float4* sQ0 = sP1 + 64;
    float4* sQ1 = sQ0 + 64;
    if (lane < 8) {
        int idx = warp * 8 + lane;
        sP0[idx] = p0; sP1[idx] = p1; sQ0[idx] = q0; sQ1[idx] = q1;
    }
    __syncthreads();
    if (tid < 8) {
        float4 tp0 = sP0[tid], tp1 = sP1[tid], tq0 = sQ0[tid], tq1 = sQ1[tid];
#pragma unroll
        for (int w = 1; w < 8; ++w) {
            float4 a = sP0[w * 8 + tid], bq = sP1[w * 8 + tid];
            float4 cq = sQ0[w * 8 + tid], dq = sQ1[w * 8 + tid];
            tp0.x += a.x; tp0.y += a.y; tp0.z += a.z; tp0.w += a.w;
            tp1.x += bq.x; tp1.y += bq.y; tp1.z += bq.z; tp1.w += bq.w;
            tq0.x += cq.x; tq0.y += cq.y; tq0.z += cq.z; tq0.w += cq.w;
            tq1.x += dq.x; tq1.y += dq.y; tq1.z += dq.z; tq1.w += dq.w;
        }
        int ba0 = b0 * 32 + tid * 4;
        int ba1 = b1 * 32 + tid * 4;
        atomicAdd(&g_s2[ba0 + 0], tp0.x); atomicAdd(&g_s2[ba0 + 1], tp0.y);
        atomicAdd(&g_s2[ba0 + 2], tp0.z); atomicAdd(&g_s2[ba0 + 3], tp0.w);
        atomicAdd(&g_s2[ba1 + 0], tp1.x); atomicAdd(&g_s2[ba1 + 1], tp1.y);
        atomicAdd(&g_s2[ba1 + 2], tp1.z); atomicAdd(&g_s2[ba1 + 3], tp1.w);
        atomicAdd(&g_q2[ba0 + 0], tq0.x); atomicAdd(&g_q2[ba0 + 1], tq0.y);
        atomicAdd(&g_q2[ba0 + 2], tq0.z); atomicAdd(&g_q2[ba0 + 3], tq0.w);
        atomicAdd(&g_q2[ba1 + 0], tq1.x); atomicAdd(&g_q2[ba1 + 1], tq1.y);
        atomicAdd(&g_q2[ba1 + 2], tq1.z); atomicAdd(&g_q2[ba1 + 3], tq1.w);
    }
}

// ---------------- 5: IN2 + ReLU + residual + ReLU + transpose ----------------
__global__ void k_final(const float* __restrict__ x, float* __restrict__ out) {
    __shared__ float sy[32 * 33];
    int tid = threadIdx.x;
    int bc = blockIdx.x;
    int b = bc >> 12, c = bc & (CC - 1);
    size_t base = ((size_t)b * CC + c) * NSEG;
    int t = tid >> 3, o0 = (tid & 7) * 4;
    float4 v = *(const float4*)&g_buf1[base + (size_t)tid * 4];
    float4 s4 = *(const float4*)&g_s2[b * 32 + o0];
    float4 q4 = *(const float4*)&g_q2[b * 32 + o0];
    float4 mu, rs;
    mu.x = s4.x * INVN; rs.x = rsqrtf(q4.x * INVN - mu.x * mu.x + 1e-5f);
    mu.y = s4.y * INVN; rs.y = rsqrtf(q4.y * INVN - mu.y * mu.y + 1e-5f);
    mu.z = s4.z * INVN; rs.z = rsqrtf(q4.z * INVN - mu.z * mu.z + 1e-5f);
    mu.w = s4.w * INVN; rs.w = rsqrtf(q4.w * INVN - mu.w * mu.w + 1e-5f);
    sy[t * 33 + o0 + 0] = fmaxf(0.f, (v.x - mu.x) * rs.x);
    sy[t * 33 + o0 + 1] = fmaxf(0.f, (v.y - mu.y) * rs.y);
    sy[t * 33 + o0 + 2] = fmaxf(0.f, (v.z - mu.z) * rs.z);
    sy[t * 33 + o0 + 3] = fmaxf(0.f, (v.w - mu.w) * rs.w);
    __syncthreads();
    int f = tid >> 3, t0 = (tid & 7) * 4;
    size_t xi = (((size_t)b * FF + f) * CC + c) * TT + t0;
    float4 xv = *(const float4*)&x[xi];
    float4 o;
    o.x = fmaxf(0.f, sy[(t0 + 0) * 33 + f] + xv.x);
    o.y = fmaxf(0.f, sy[(t0 + 1) * 33 + f] + xv.y);
    o.z = fmaxf(0.f, sy[(t0 + 2) * 33 + f] + xv.z);
    o.w = fmaxf(0.f, sy[(t0 + 3) * 33 + f] + xv.w);
    *(float4*)&out[xi] = o;
}

// ---------------- launch ----------------
extern "C" void kernel_launch(void* const* d_in, const int* in_sizes, int n_in,
                              void* d_out, int out_size) {
    const float* x    = (const float*)d_in[0];
    const int*   ei   = (const int*)d_in[1];
    const float* ew   = (const float*)d_in[2];
    const float* W    = (const float*)d_in[3];
    const float* gcnb = (const float*)d_in[4];
    const float* cw   = (const float*)d_in[5];
    const float* cb   = (const float*)d_in[6];
    float* out = (float*)d_out;

    const int conv_smem = 73728 + 512 + 8 * 1280 * 8;   // 156160
    cudaFuncSetAttribute(k_conv, cudaFuncAttributeMaxDynamicSharedMemorySize, conv_smem);

    // 5 launches; k_conv stays 4th => profiled next round.
    k_xlin <<<BB * CC, 256>>>(x, W);
    k_setup<<<1, 1024>>>(ei, ew);
    k_agg  <<<CC, 256>>>(gcnb);
    k_conv <<<(CC / 8) * 2, 256, conv_smem>>>(cw, cb);
    k_final<<<BB * CC, 256>>>(x, out);
}